// round 7
// baseline (speedup 1.0000x reference)
#include <cuda_runtime.h>
#include <math.h>

// Problem dims
#define BB 2
#define CC 256
#define LL 4096
#define HH 8
#define DD 32
#define NBH 16
#define NPTS 65536   // 16*4096
#define KCL 256      // clusters / top_k
#define NITER 10

// ---------------- scratch ----------------
__device__ float g_xc[BB*CC*LL];      // ctx after LN
__device__ float g_xq[BB*CC*LL];      // query_source after LN
__device__ float g_kv[BB*2*CC*LL];    // kv projection
__device__ float g_qp[BB*CC*LL];      // q projection (pre-fold)
__device__ float g_qt[NPTS*DD];       // q  [bh][l][d], l2-normalized
__device__ float g_kt[NPTS*DD];       // k  [bh][l][d], l2-normalized
__device__ float g_vt[NPTS*DD];       // v  [bh][l][d]
__device__ float g_cent[KCL*DD];
__device__ float g_cnorm[KCL];
__device__ int   g_assign[NPTS];
__device__ int   g_bcnt[256*KCL];     // per-block per-cluster counts
__device__ int   g_bstart[256*KCL];   // scatter start offsets
__device__ int   g_cbase[KCL];
__device__ int   g_ctot[KCL];
__device__ int   g_list[NPTS];        // per-cluster ordered point lists
__device__ float g_kdist[NPTS];
__device__ int   g_topk[NBH*KCL];
__device__ float g_ksel[NBH*KCL*DD];
__device__ float g_vsel[NBH*KCL*DD];
__device__ float g_oin[BB*CC*LL];     // attention out, unfolded to (b,256,L)
__device__ float g_o2[BB*CC*LL];      // w_out result

// XLA:CPU-style vectorized row reduction over 32 elements:
// 4 lane partial sums (NEON width), chunks ascending, then split-halves
// horizontal tree: (s0+s2)+(s1+s3).
__device__ __forceinline__ float row_reduce_sq(const float* v) {
    float s0 = 0.f, s1 = 0.f, s2 = 0.f, s3 = 0.f;
#pragma unroll
    for (int i = 0; i < 8; i++) {
        s0 = fmaf(v[4*i+0], v[4*i+0], s0);
        s1 = fmaf(v[4*i+1], v[4*i+1], s1);
        s2 = fmaf(v[4*i+2], v[4*i+2], s2);
        s3 = fmaf(v[4*i+3], v[4*i+3], s3);
    }
    return __fadd_rn(__fadd_rn(s0, s2), __fadd_rn(s1, s3));
}

// ---------------- channel layer norm (two-pass var, fma-contracted squares) ----------------
__global__ void ln_kernel(const float* __restrict__ src,
                          const float* __restrict__ gamma,
                          const float* __restrict__ beta, int mode) {
    float* dst = (mode == 0) ? g_xc : g_xq;
    int n = blockIdx.x * blockDim.x + threadIdx.x;   // 0..8191
    int b = n >> 12, l = n & 4095;
    const float* colp = src + (size_t)b * CC * LL + l;
    float s = 0.f;
    for (int c = 0; c < CC; c++) s = __fadd_rn(s, colp[(size_t)c * LL]);
    float mean = __fdiv_rn(s, 256.f);
    float acc = 0.f;
    for (int c = 0; c < CC; c++) {
        float d = __fsub_rn(colp[(size_t)c * LL], mean);
        acc = fmaf(d, d, acc);                 // contracted
    }
    float var = __fdiv_rn(acc, 256.f);
    float denom = __fadd_rn(sqrtf(var), 1e-6f);
    float* dcol = dst + (size_t)b * CC * LL + l;
    for (int c = 0; c < CC; c++) {
        float v = colp[(size_t)c * LL];
        float y = __fadd_rn(__fdiv_rn(__fmul_rn(gamma[c], __fsub_rn(v, mean)), denom), beta[c]);
        dcol[(size_t)c * LL] = y;
    }
}

// ---------------- tiled fp32 GEMM (sequential ascending-k FMA chain per output) ----------------
// Y[b][m][l] = sum_c W[m][c] X[b][c][l]; grid: (8192/64, M/64); block 256
__global__ void gemm_kernel(const float* __restrict__ W, int mode) {
    const float* X; float* Y; int M;
    if (mode == 0)      { X = g_xc;  Y = g_kv; M = 512; }
    else if (mode == 1) { X = g_xq;  Y = g_qp; M = 256; }
    else                { X = g_oin; Y = g_o2; M = 256; }

    __shared__ float As[16][64];
    __shared__ float Bs[16][64];

    int n0 = blockIdx.x * 64;          // global column (b*4096 + l)
    int m0 = blockIdx.y * 64;
    int b  = n0 >> 12;
    int l0 = n0 & 4095;
    const float* Xb = X + (size_t)b * CC * LL;
    float* Yb = Y + (size_t)b * M * LL;

    int tid = threadIdx.x;
    int tx = tid & 15;   // n micro
    int ty = tid >> 4;   // m micro
    float acc[4][4];
#pragma unroll
    for (int i = 0; i < 4; i++)
#pragma unroll
        for (int j = 0; j < 4; j++) acc[i][j] = 0.f;

    for (int k0 = 0; k0 < CC; k0 += 16) {
#pragma unroll
        for (int idx = tid; idx < 64 * 16; idx += 256) {
            int i = idx >> 4, j = idx & 15;      // i: m, j: k
            As[j][i] = W[(size_t)(m0 + i) * CC + k0 + j];
        }
#pragma unroll
        for (int idx = tid; idx < 16 * 64; idx += 256) {
            int i = idx >> 6, j = idx & 63;      // i: k, j: n
            Bs[i][j] = Xb[(size_t)(k0 + i) * LL + l0 + j];
        }
        __syncthreads();
#pragma unroll
        for (int kk = 0; kk < 16; kk++) {
            float a[4], bb[4];
            *(float4*)a  = *(const float4*)&As[kk][ty * 4];
            *(float4*)bb = *(const float4*)&Bs[kk][tx * 4];
#pragma unroll
            for (int i = 0; i < 4; i++)
#pragma unroll
                for (int j = 0; j < 4; j++) acc[i][j] = fmaf(a[i], bb[j], acc[i][j]);
        }
        __syncthreads();
    }
#pragma unroll
    for (int i = 0; i < 4; i++) {
        float4 o = make_float4(acc[i][0], acc[i][1], acc[i][2], acc[i][3]);
        *(float4*)&Yb[(size_t)(m0 + ty * 4 + i) * LL + l0 + tx * 4] = o;
    }
}

// ---------------- fold + optional l2norm + transpose (column reduce: sequential) ----------------
__global__ void fold_kernel(int mode) {
    const float* src; float* dst; int rows, off, doNorm;
    if (mode == 0)      { src = g_qp; dst = g_qt; rows = 256; off = 0;   doNorm = 1; }
    else if (mode == 1) { src = g_kv; dst = g_kt; rows = 512; off = 0;   doNorm = 1; }
    else                { src = g_kv; dst = g_vt; rows = 512; off = 256; doNorm = 0; }

    __shared__ float s[32][33];
    __shared__ float nrm[32];
    int bh = blockIdx.y;
    int b = bh >> 3, h = bh & 7;
    int l0 = blockIdx.x * 32;
    int x = threadIdx.x, y = threadIdx.y;   // load: x = l, y = d

    s[y][x] = src[((size_t)b * rows + off + h * 32 + y) * LL + l0 + x];
    __syncthreads();
    if (y == 0) {
        float ss = 0.f;
#pragma unroll
        for (int d = 0; d < 32; d++) { float v = s[d][x]; ss = fmaf(v, v, ss); }
        nrm[x] = fmaxf(sqrtf(ss), 1e-12f);
    }
    __syncthreads();
    // write: x = d, y = l
    float v = s[x][y];
    if (doNorm) v = __fdiv_rn(v, nrm[y]);
    dst[((size_t)bh * LL + l0 + y) * DD + x] = v;
}

// ---------------- kmeans init: centroids = first 256 q rows; VF4-tree cnorm ----------------
__global__ void kinit_kernel() {
    __shared__ float cs[DD];
    int j = blockIdx.x, d = threadIdx.x;
    float v = g_qt[j * DD + d];
    g_cent[j * DD + d] = v;
    cs[d] = v;
    __syncthreads();
    if (d == 0) g_cnorm[j] = row_reduce_sq(cs);
}

// ---------------- assignment (mode 0: q points; mode 1: k points + L1 dist) ----------------
// dist = xx - 2*dot + cn ; dot sequential ascending-k FMA (Eigen order).
// xx cancels in argmin (constant per point) so its order is irrelevant.
__global__ void assign_kernel(int mode) {
    __shared__ float sc[KCL * DD];
    __shared__ float scn[KCL];
    int tid = threadIdx.x;
    for (int i = tid; i < KCL * DD; i += 256) sc[i] = g_cent[i];
    if (tid < KCL) scn[tid] = g_cnorm[tid];
    __syncthreads();

    const float* pts = (mode == 0) ? g_qt : g_kt;
    int p = blockIdx.x * 256 + tid;

    float x[32];
    const float4* xp = (const float4*)(pts + (size_t)p * DD);
#pragma unroll
    for (int i = 0; i < 8; i++) ((float4*)x)[i] = xp[i];
    float xx = 0.f;
#pragma unroll
    for (int d = 0; d < 32; d++) xx = fmaf(x[d], x[d], xx);

    float best = 3.4e38f; int bj = 0;
    for (int j = 0; j < KCL; j++) {
        float dot = 0.f;
        const float4* cp = (const float4*)(sc + j * DD);
#pragma unroll
        for (int i = 0; i < 8; i++) {
            float4 c4 = cp[i];
            dot = fmaf(x[i*4+0], c4.x, dot);
            dot = fmaf(x[i*4+1], c4.y, dot);
            dot = fmaf(x[i*4+2], c4.z, dot);
            dot = fmaf(x[i*4+3], c4.w, dot);
        }
        float sdist = __fadd_rn(__fsub_rn(xx, __fmul_rn(2.f, dot)), scn[j]);
        if (sdist < best) { best = sdist; bj = j; }   // first min wins (argmin)
    }
    g_assign[p] = bj;

    if (mode == 1) {
        // L1 distance: VF4 lane partials (plain adds), (s0+s2)+(s1+s3) tree
        const float* corig = g_cent + bj * DD;
        float s0 = 0.f, s1 = 0.f, s2 = 0.f, s3 = 0.f;
#pragma unroll
        for (int i = 0; i < 8; i++) {
            s0 = __fadd_rn(s0, fabsf(__fsub_rn(corig[4*i+0], x[4*i+0])));
            s1 = __fadd_rn(s1, fabsf(__fsub_rn(corig[4*i+1], x[4*i+1])));
            s2 = __fadd_rn(s2, fabsf(__fsub_rn(corig[4*i+2], x[4*i+2])));
            s3 = __fadd_rn(s3, fabsf(__fsub_rn(corig[4*i+3], x[4*i+3])));
        }
        g_kdist[p] = __fadd_rn(__fadd_rn(s0, s2), __fadd_rn(s1, s3));
    }
}

// ---------------- deterministic segment-sum pipeline (XLA scatter order) ----------------
// A: per-block histogram (integer counts — order independent, exact)
__global__ void count_kernel() {
    __shared__ int cnt[KCL];
    int tid = threadIdx.x;
    cnt[tid] = 0;
    __syncthreads();
    atomicAdd(&cnt[g_assign[blockIdx.x * 256 + tid]], 1);
    __syncthreads();
    g_bcnt[blockIdx.x * KCL + tid] = cnt[tid];
}

// B: offsets — single block, 256 threads (one per cluster)
__global__ void offset_kernel() {
    __shared__ int tot[KCL];
    __shared__ int base[KCL];
    int j = threadIdx.x;
    int running = 0;
    for (int b = 0; b < 256; b++) {
        int t = g_bcnt[b * KCL + j];
        g_bstart[b * KCL + j] = running;
        running += t;
    }
    tot[j] = running;
    __syncthreads();
    if (j == 0) {
        int acc = 0;
        for (int jj = 0; jj < KCL; jj++) { base[jj] = acc; acc += tot[jj]; }
    }
    __syncthreads();
    g_cbase[j] = base[j];
    g_ctot[j]  = tot[j];
    for (int b = 0; b < 256; b++) g_bstart[b * KCL + j] += base[j];
}

// C: order-preserving scatter — serial within each block of 256 points
__global__ void scatter_kernel() {
    __shared__ int ofs[KCL];
    __shared__ int abuf[256];
    int tid = threadIdx.x;
    int blk = blockIdx.x;
    ofs[tid]  = g_bstart[blk * KCL + tid];
    abuf[tid] = g_assign[blk * 256 + tid];
    __syncthreads();
    if (tid == 0) {
        int p0 = blk * 256;
        for (int i = 0; i < 256; i++) {
            int a = abuf[i];
            g_list[ofs[a]++] = p0 + i;
        }
    }
}

// D: per-cluster sequential (ascending point order) sum -> centroid + VF4-tree cnorm
__global__ void centroid_kernel() {
    __shared__ float cs[DD];
    int j = blockIdx.x, d = threadIdx.x;
    int base = g_cbase[j];
    int tot  = g_ctot[j];
    float s = 0.f;
    for (int i = 0; i < tot; i++) {
        int p = g_list[base + i];
        s = __fadd_rn(s, g_qt[(size_t)p * DD + d]);
    }
    float old = g_cent[j * DD + d];
    float cntf = (float)tot;
    float newc = (tot > 0) ? __fdiv_rn(s, fmaxf(cntf, 1.f)) : old;
    g_cent[j * DD + d] = newc;
    cs[d] = newc;
    __syncthreads();
    if (d == 0) g_cnorm[j] = row_reduce_sq(cs);
}

// ---------------- top-256 by k_dist (desc value, asc index) via bitonic sort ----------------
__global__ void topk_kernel() {
    __shared__ unsigned long long s[LL];
    int bh = blockIdx.x, tid = threadIdx.x;   // 1024 threads
    for (int i = tid; i < LL; i += 1024) {
        float v = g_kdist[(size_t)bh * LL + i];
        unsigned u = __float_as_uint(v);
        u = (u & 0x80000000u) ? ~u : (u | 0x80000000u);  // ascending map
        u = ~u;                                          // descending
        s[i] = ((unsigned long long)u << 32) | (unsigned)i;
    }
    __syncthreads();
    for (int k = 2; k <= LL; k <<= 1) {
        for (int j = k >> 1; j > 0; j >>= 1) {
            for (int i = tid; i < LL; i += 1024) {
                int ixj = i ^ j;
                if (ixj > i) {
                    bool up = ((i & k) == 0);
                    unsigned long long a = s[i], b = s[ixj];
                    if ((a > b) == up) { s[i] = b; s[ixj] = a; }
                }
            }
            __syncthreads();
        }
    }
    if (tid < KCL) g_topk[bh * KCL + tid] = (int)(s[tid] & 0xffffffffu);
}

// ---------------- gather selected k/v ----------------
__global__ void gather_kernel() {
    int idx = blockIdx.x * 256 + threadIdx.x;   // 16*256*32
    int d = idx & 31;
    int r = idx >> 5;           // bh*256 + t
    int bh = r >> 8;
    int src = g_topk[r];
    g_ksel[idx] = g_kt[((size_t)bh * LL + src) * DD + d];
    g_vsel[idx] = g_vt[((size_t)bh * LL + src) * DD + d];
}

// ---------------- attention (online softmax; post-decision, noise-tolerant) ----------------
__global__ void attn_kernel() {
    __shared__ float ks[128 * DD];
    __shared__ float vs[128 * DD];
    int bh = blockIdx.y;
    int b = bh >> 3, h = bh & 7;
    int l = blockIdx.x * 128 + threadIdx.x;

    float q[32];
    const float4* qp = (const float4*)(g_qt + ((size_t)bh * LL + l) * DD);
#pragma unroll
    for (int i = 0; i < 8; i++) ((float4*)q)[i] = qp[i];

    float m = -1e30f, lsum = 0.f;
    float acc[32];
#pragma unroll
    for (int d = 0; d < 32; d++) acc[d] = 0.f;

    for (int c = 0; c < 2; c++) {
        __syncthreads();
        for (int i = threadIdx.x; i < 128 * DD; i += 128) {
            ks[i] = g_ksel[(size_t)bh * KCL * DD + c * 128 * DD + i];
            vs[i] = g_vsel[(size_t)bh * KCL * DD + c * 128 * DD + i];
        }
        __syncthreads();
        for (int j = 0; j < 128; j++) {
            float dot = 0.f;
            const float4* kp = (const float4*)(ks + j * DD);
#pragma unroll
            for (int i = 0; i < 8; i++) {
                float4 k4 = kp[i];
                dot = fmaf(q[i*4+0], k4.x, dot);
                dot = fmaf(q[i*4+1], k4.y, dot);
                dot = fmaf(q[i*4+2], k4.z, dot);
                dot = fmaf(q[i*4+3], k4.w, dot);
            }
            if (dot > m) {
                float corr = expf(m - dot);
                lsum *= corr;
#pragma unroll
                for (int d = 0; d < 32; d++) acc[d] *= corr;
                m = dot;
            }
            float p = expf(dot - m);
            lsum += p;
            const float4* vp = (const float4*)(vs + j * DD);
#pragma unroll
            for (int i = 0; i < 8; i++) {
                float4 v4 = vp[i];
                acc[i*4+0] = fmaf(p, v4.x, acc[i*4+0]);
                acc[i*4+1] = fmaf(p, v4.y, acc[i*4+1]);
                acc[i*4+2] = fmaf(p, v4.z, acc[i*4+2]);
                acc[i*4+3] = fmaf(p, v4.w, acc[i*4+3]);
            }
        }
    }
    float inv = 1.f / lsum;
#pragma unroll
    for (int d = 0; d < 32; d++) {
        g_oin[((size_t)b * CC + h * 32 + d) * LL + l] = acc[d] * inv;
    }
}

// ---------------- final LN + scaled residual (two-pass var, fma squares) ----------------
__global__ void final_kernel(const float* __restrict__ qsrc,
                             const float* __restrict__ gamma,
                             const float* __restrict__ beta,
                             const float* __restrict__ gs,
                             float* __restrict__ out) {
    int n = blockIdx.x * blockDim.x + threadIdx.x;
    int b = n >> 12, l = n & 4095;
    const float* colp = g_o2 + (size_t)b * CC * LL + l;
    float s = 0.f;
    for (int c = 0; c < CC; c++) s = __fadd_rn(s, colp[(size_t)c * LL]);
    float mean = __fdiv_rn(s, 256.f);
    float acc = 0.f;
    for (int c = 0; c < CC; c++) {
        float d = __fsub_rn(colp[(size_t)c * LL], mean);
        acc = fmaf(d, d, acc);
    }
    float var = __fdiv_rn(acc, 256.f);
    float denom = __fadd_rn(sqrtf(var), 1e-6f);
    float g = gs[0];
    for (int c = 0; c < CC; c++) {
        float v = colp[(size_t)c * LL];
        float y = __fadd_rn(__fdiv_rn(__fmul_rn(gamma[c], __fsub_rn(v, mean)), denom), beta[c]);
        out[(size_t)b * CC * LL + (size_t)c * LL + l] =
            fmaf(g, y, qsrc[(size_t)b * CC * LL + (size_t)c * LL + l]);
    }
}

// ---------------- launch ----------------
extern "C" void kernel_launch(void* const* d_in, const int* in_sizes, int n_in,
                              void* d_out, int out_size) {
    const float* qsrc   = (const float*)d_in[0];
    const float* ctx    = (const float*)d_in[1];
    const float* w_q    = (const float*)d_in[2];
    const float* w_kv   = (const float*)d_in[3];
    const float* w_out  = (const float*)d_in[4];
    const float* lnc_g  = (const float*)d_in[5];
    const float* lnc_b  = (const float*)d_in[6];
    const float* lnq_g  = (const float*)d_in[7];
    const float* lnq_b  = (const float*)d_in[8];
    const float* lno_g  = (const float*)d_in[9];
    const float* lno_b  = (const float*)d_in[10];
    const float* gs     = (const float*)d_in[11];
    float* out = (float*)d_out;

    // LN both inputs
    ln_kernel<<<32, 256>>>(ctx,  lnc_g, lnc_b, 0);
    ln_kernel<<<32, 256>>>(qsrc, lnq_g, lnq_b, 1);

    // projections
    gemm_kernel<<<dim3(128, 8), 256>>>(w_kv, 0);   // kv: 512 rows
    gemm_kernel<<<dim3(128, 4), 256>>>(w_q,  1);   // q: 256 rows

    // fold + l2norm + transpose
    fold_kernel<<<dim3(128, NBH), dim3(32, 32)>>>(0);  // q
    fold_kernel<<<dim3(128, NBH), dim3(32, 32)>>>(1);  // k
    fold_kernel<<<dim3(128, NBH), dim3(32, 32)>>>(2);  // v

    // kmeans (deterministic, reference-order arithmetic)
    kinit_kernel<<<KCL, 32>>>();
    for (int it = 0; it < NITER; it++) {
        assign_kernel<<<NPTS / 256, 256>>>(0);
        count_kernel<<<256, 256>>>();
        offset_kernel<<<1, 256>>>();
        scatter_kernel<<<256, 256>>>();
        centroid_kernel<<<KCL, 32>>>();
    }

    // k assignment + L1 distance to its centroid
    assign_kernel<<<NPTS / 256, 256>>>(1);

    // top-256 per bh, gather
    topk_kernel<<<NBH, 1024>>>();
    gather_kernel<<<NBH * KCL * DD / 256, 256>>>();

    // attention + unfold
    attn_kernel<<<dim3(32, NBH), 128>>>();

    // output projection
    gemm_kernel<<<dim3(128, 4), 256>>>(w_out, 2);

    // final LN + residual
    final_kernel<<<32, 256>>>(qsrc, lno_g, lno_b, gs, out);
}

// round 8
// speedup vs baseline: 1.1231x; 1.1231x over previous
#include <cuda_runtime.h>
#include <math.h>

// Problem dims
#define BB 2
#define CC 256
#define LL 4096
#define HH 8
#define DD 32
#define NBH 16
#define NPTS 65536   // 16*4096
#define KCL 256      // clusters / top_k
#define NITER 10

// ---------------- scratch ----------------
__device__ float g_xc[BB*CC*LL];      // ctx after LN
__device__ float g_xq[BB*CC*LL];      // query_source after LN
__device__ float g_kv[BB*2*CC*LL];    // kv projection
__device__ float g_qp[BB*CC*LL];      // q projection (pre-fold)
__device__ float g_qt[NPTS*DD];       // q  [bh][l][d], l2-normalized
__device__ float g_kt[NPTS*DD];       // k  [bh][l][d], l2-normalized
__device__ float g_vt[NPTS*DD];       // v  [bh][l][d]
__device__ float g_cent[KCL*DD];
__device__ float g_cnorm[KCL];
__device__ int   g_assign[NPTS];
__device__ int   g_bcnt[256*KCL];     // per-block per-cluster counts
__device__ int   g_bstart[256*KCL];   // local (within-cluster) prefix across blocks
__device__ int   g_cbase[KCL];
__device__ int   g_ctot[KCL];
__device__ int   g_list[NPTS];        // per-cluster ordered point lists
__device__ float g_kdist[NPTS];
__device__ int   g_topk[NBH*KCL];
__device__ float g_ksel[NBH*KCL*DD];
__device__ float g_vsel[NBH*KCL*DD];
__device__ float g_oin[BB*CC*LL];     // attention out, unfolded to (b,256,L)
__device__ float g_o2[BB*CC*LL];      // w_out result

// XLA:CPU-style vectorized row reduction over 32 elements:
// 4 lane partial sums, chunks ascending, then (s0+s2)+(s1+s3).
__device__ __forceinline__ float row_reduce_sq(const float* v) {
    float s0 = 0.f, s1 = 0.f, s2 = 0.f, s3 = 0.f;
#pragma unroll
    for (int i = 0; i < 8; i++) {
        s0 = fmaf(v[4*i+0], v[4*i+0], s0);
        s1 = fmaf(v[4*i+1], v[4*i+1], s1);
        s2 = fmaf(v[4*i+2], v[4*i+2], s2);
        s3 = fmaf(v[4*i+3], v[4*i+3], s3);
    }
    return __fadd_rn(__fadd_rn(s0, s2), __fadd_rn(s1, s3));
}

// ---------------- channel layer norm (two-pass var, fma-contracted squares) ----------------
__global__ void ln_kernel(const float* __restrict__ src,
                          const float* __restrict__ gamma,
                          const float* __restrict__ beta, int mode) {
    float* dst = (mode == 0) ? g_xc : g_xq;
    int n = blockIdx.x * blockDim.x + threadIdx.x;   // 0..8191
    int b = n >> 12, l = n & 4095;
    const float* colp = src + (size_t)b * CC * LL + l;
    float s = 0.f;
    for (int c = 0; c < CC; c++) s = __fadd_rn(s, colp[(size_t)c * LL]);
    float mean = __fdiv_rn(s, 256.f);
    float acc = 0.f;
    for (int c = 0; c < CC; c++) {
        float d = __fsub_rn(colp[(size_t)c * LL], mean);
        acc = fmaf(d, d, acc);
    }
    float var = __fdiv_rn(acc, 256.f);
    float denom = __fadd_rn(sqrtf(var), 1e-6f);
    float* dcol = dst + (size_t)b * CC * LL + l;
    for (int c = 0; c < CC; c++) {
        float v = colp[(size_t)c * LL];
        float y = __fadd_rn(__fdiv_rn(__fmul_rn(gamma[c], __fsub_rn(v, mean)), denom), beta[c]);
        dcol[(size_t)c * LL] = y;
    }
}

// ---------------- tiled fp32 GEMM (sequential ascending-k FMA chain per output) ----------------
// Y[b][m][l] = sum_c W[m][c] X[b][c][l]; grid: (8192/64, M/64); block 256
__global__ void gemm_kernel(const float* __restrict__ W, int mode) {
    const float* X; float* Y; int M;
    if (mode == 0)      { X = g_xc;  Y = g_kv; M = 512; }
    else if (mode == 1) { X = g_xq;  Y = g_qp; M = 256; }
    else                { X = g_oin; Y = g_o2; M = 256; }

    __shared__ float As[16][68];   // padded: kills 16-way bank conflict on fill
    __shared__ float Bs[16][64];

    int n0 = blockIdx.x * 64;          // global column (b*4096 + l)
    int m0 = blockIdx.y * 64;
    int b  = n0 >> 12;
    int l0 = n0 & 4095;
    const float* Xb = X + (size_t)b * CC * LL;
    float* Yb = Y + (size_t)b * M * LL;

    int tid = threadIdx.x;
    int tx = tid & 15;   // n micro
    int ty = tid >> 4;   // m micro
    float acc[4][4];
#pragma unroll
    for (int i = 0; i < 4; i++)
#pragma unroll
        for (int j = 0; j < 4; j++) acc[i][j] = 0.f;

    for (int k0 = 0; k0 < CC; k0 += 16) {
#pragma unroll
        for (int idx = tid; idx < 64 * 16; idx += 256) {
            int i = idx >> 4, j = idx & 15;      // i: m, j: k
            As[j][i] = W[(size_t)(m0 + i) * CC + k0 + j];
        }
#pragma unroll
        for (int idx = tid; idx < 16 * 64; idx += 256) {
            int i = idx >> 6, j = idx & 63;      // i: k, j: n
            Bs[i][j] = Xb[(size_t)(k0 + i) * LL + l0 + j];
        }
        __syncthreads();
#pragma unroll
        for (int kk = 0; kk < 16; kk++) {
            float a[4], bb[4];
            *(float4*)a  = *(const float4*)&As[kk][ty * 4];
            *(float4*)bb = *(const float4*)&Bs[kk][tx * 4];
#pragma unroll
            for (int i = 0; i < 4; i++)
#pragma unroll
                for (int j = 0; j < 4; j++) acc[i][j] = fmaf(a[i], bb[j], acc[i][j]);
        }
        __syncthreads();
    }
#pragma unroll
    for (int i = 0; i < 4; i++) {
        float4 o = make_float4(acc[i][0], acc[i][1], acc[i][2], acc[i][3]);
        *(float4*)&Yb[(size_t)(m0 + ty * 4 + i) * LL + l0 + tx * 4] = o;
    }
}

// ---------------- fold + optional l2norm + transpose ----------------
__global__ void fold_kernel(int mode) {
    const float* src; float* dst; int rows, off, doNorm;
    if (mode == 0)      { src = g_qp; dst = g_qt; rows = 256; off = 0;   doNorm = 1; }
    else if (mode == 1) { src = g_kv; dst = g_kt; rows = 512; off = 0;   doNorm = 1; }
    else                { src = g_kv; dst = g_vt; rows = 512; off = 256; doNorm = 0; }

    __shared__ float s[32][33];
    __shared__ float nrm[32];
    int bh = blockIdx.y;
    int b = bh >> 3, h = bh & 7;
    int l0 = blockIdx.x * 32;
    int x = threadIdx.x, y = threadIdx.y;   // load: x = l, y = d

    s[y][x] = src[((size_t)b * rows + off + h * 32 + y) * LL + l0 + x];
    __syncthreads();
    if (y == 0) {
        float ss = 0.f;
#pragma unroll
        for (int d = 0; d < 32; d++) { float v = s[d][x]; ss = fmaf(v, v, ss); }
        nrm[x] = fmaxf(sqrtf(ss), 1e-12f);
    }
    __syncthreads();
    // write: x = d, y = l
    float v = s[x][y];
    if (doNorm) v = __fdiv_rn(v, nrm[y]);
    dst[((size_t)bh * LL + l0 + y) * DD + x] = v;
}

// ---------------- kmeans init: centroids = first 256 q rows; VF4-tree cnorm ----------------
__global__ void kinit_kernel() {
    __shared__ float cs[DD];
    int j = blockIdx.x, d = threadIdx.x;
    float v = g_qt[j * DD + d];
    g_cent[j * DD + d] = v;
    cs[d] = v;
    __syncthreads();
    if (d == 0) g_cnorm[j] = row_reduce_sq(cs);
}

// ---------------- assignment (mode 0: q points + block histogram; mode 1: k + L1) ----------------
// dist = xx - 2*dot + cn ; dot sequential ascending-k FMA (Eigen order), bit-frozen.
__global__ void assign_kernel(int mode) {
    __shared__ float sc[KCL * DD];
    __shared__ float scn[KCL];
    __shared__ int   cnt[KCL];
    int tid = threadIdx.x;
    for (int i = tid; i < KCL * DD; i += 256) sc[i] = g_cent[i];
    if (tid < KCL) { scn[tid] = g_cnorm[tid]; cnt[tid] = 0; }
    __syncthreads();

    const float* pts = (mode == 0) ? g_qt : g_kt;
    int p = blockIdx.x * 256 + tid;

    float x[32];
    const float4* xp = (const float4*)(pts + (size_t)p * DD);
#pragma unroll
    for (int i = 0; i < 8; i++) ((float4*)x)[i] = xp[i];
    float xx = 0.f;
#pragma unroll
    for (int d = 0; d < 32; d++) xx = fmaf(x[d], x[d], xx);

    float best = 3.4e38f; int bj = 0;
    // unroll by 2: two independent chains, each dot is the exact ascending-k FMA chain
    for (int j = 0; j < KCL; j += 2) {
        float dot0 = 0.f, dot1 = 0.f;
        const float4* cp0 = (const float4*)(sc + j * DD);
        const float4* cp1 = (const float4*)(sc + (j + 1) * DD);
#pragma unroll
        for (int i = 0; i < 8; i++) {
            float4 a4 = cp0[i];
            float4 b4 = cp1[i];
            dot0 = fmaf(x[i*4+0], a4.x, dot0);
            dot0 = fmaf(x[i*4+1], a4.y, dot0);
            dot0 = fmaf(x[i*4+2], a4.z, dot0);
            dot0 = fmaf(x[i*4+3], a4.w, dot0);
            dot1 = fmaf(x[i*4+0], b4.x, dot1);
            dot1 = fmaf(x[i*4+1], b4.y, dot1);
            dot1 = fmaf(x[i*4+2], b4.z, dot1);
            dot1 = fmaf(x[i*4+3], b4.w, dot1);
        }
        float d0 = __fadd_rn(__fsub_rn(xx, __fmul_rn(2.f, dot0)), scn[j]);
        float d1 = __fadd_rn(__fsub_rn(xx, __fmul_rn(2.f, dot1)), scn[j + 1]);
        if (d0 < best) { best = d0; bj = j; }       // first min wins (argmin)
        if (d1 < best) { best = d1; bj = j + 1; }
    }
    g_assign[p] = bj;

    if (mode == 0) {
        // per-block integer histogram (exact), replaces count_kernel
        unsigned m = __match_any_sync(0xffffffffu, bj);
        int lane = tid & 31;
        if (lane == __ffs(m) - 1) atomicAdd(&cnt[bj], __popc(m));
        __syncthreads();
        for (int i = tid; i < KCL; i += 256) g_bcnt[blockIdx.x * KCL + i] = cnt[i];
    } else {
        // L1 distance: VF4 lane partials (plain adds), (s0+s2)+(s1+s3) tree
        const float* corig = g_cent + bj * DD;
        float s0 = 0.f, s1 = 0.f, s2 = 0.f, s3 = 0.f;
#pragma unroll
        for (int i = 0; i < 8; i++) {
            s0 = __fadd_rn(s0, fabsf(__fsub_rn(corig[4*i+0], x[4*i+0])));
            s1 = __fadd_rn(s1, fabsf(__fsub_rn(corig[4*i+1], x[4*i+1])));
            s2 = __fadd_rn(s2, fabsf(__fsub_rn(corig[4*i+2], x[4*i+2])));
            s3 = __fadd_rn(s3, fabsf(__fsub_rn(corig[4*i+3], x[4*i+3])));
        }
        g_kdist[p] = __fadd_rn(__fadd_rn(s0, s2), __fadd_rn(s1, s3));
    }
}

// ---------------- offsets: parallel scan (integers, exact) ----------------
// g_bstart[b][j] = sum_{b'<b} cnt[b'][j]  (local); g_cbase[j] = sum_{j'<j} tot[j']
__global__ void offset_kernel() {   // 1 block, 256 threads
    __shared__ int wsum[8];
    int j = threadIdx.x;
    int lane = j & 31, w = j >> 5;
    int running = 0;
    for (int b = 0; b < 256; b++) {
        int t = g_bcnt[b * KCL + j];       // coalesced across j
        g_bstart[b * KCL + j] = running;
        running += t;
    }
    int v = running;                        // tot[j]
    // block-wide exclusive scan over 256 totals
    int s = v;
#pragma unroll
    for (int o = 1; o < 32; o <<= 1) {
        int n = __shfl_up_sync(0xffffffffu, s, o);
        if (lane >= o) s += n;
    }
    if (lane == 31) wsum[w] = s;
    __syncthreads();
    int woff = 0;
    for (int ww = 0; ww < w; ww++) woff += wsum[ww];
    g_cbase[j] = woff + s - v;
    g_ctot[j]  = v;
}

// ---------------- scatter: parallel, order-preserving (stable ranks) ----------------
__global__ void scatter_kernel() {
    __shared__ int whist[8][KCL];     // per-warp cluster counts -> exclusive prefix
    int tid = threadIdx.x, blk = blockIdx.x;
    int w = tid >> 5, lane = tid & 31;
    for (int i = tid; i < 8 * KCL; i += 256) ((int*)whist)[i] = 0;
    __syncthreads();
    int p = blk * 256 + tid;
    int a = g_assign[p];
    unsigned m = __match_any_sync(0xffffffffu, a);
    int rank = __popc(m & ((1u << lane) - 1u));
    if (lane == __ffs(m) - 1) whist[w][a] = __popc(m);
    __syncthreads();
    // exclusive prefix across warps, per cluster (thread tid handles cluster tid)
    int c = tid, s = 0;
#pragma unroll
    for (int ww = 0; ww < 8; ww++) { int t = whist[ww][c]; whist[ww][c] = s; s += t; }
    __syncthreads();
    int pos = g_cbase[a] + g_bstart[blk * KCL + a] + whist[w][a] + rank;
    g_list[pos] = p;
}

// ---------------- centroids: 8 clusters/block, sequential add chain, batched loads ----------------
__global__ void centroid_kernel() {   // grid 32, block 256
    __shared__ float cs[8][DD];
    int w = threadIdx.x >> 5, d = threadIdx.x & 31;
    int j = blockIdx.x * 8 + w;
    int base = g_cbase[j];
    int tot  = g_ctot[j];
    float s = 0.f;
    int i = 0;
    for (; i + 4 <= tot; i += 4) {
        int p0 = g_list[base + i + 0];
        int p1 = g_list[base + i + 1];
        int p2 = g_list[base + i + 2];
        int p3 = g_list[base + i + 3];
        float x0 = g_qt[(size_t)p0 * DD + d];
        float x1 = g_qt[(size_t)p1 * DD + d];
        float x2 = g_qt[(size_t)p2 * DD + d];
        float x3 = g_qt[(size_t)p3 * DD + d];
        s = __fadd_rn(s, x0);
        s = __fadd_rn(s, x1);
        s = __fadd_rn(s, x2);
        s = __fadd_rn(s, x3);
    }
    for (; i < tot; i++)
        s = __fadd_rn(s, g_qt[(size_t)g_list[base + i] * DD + d]);

    float old = g_cent[j * DD + d];
    float cntf = (float)tot;
    float newc = (tot > 0) ? __fdiv_rn(s, fmaxf(cntf, 1.f)) : old;
    g_cent[j * DD + d] = newc;
    cs[w][d] = newc;
    __syncwarp();
    if (d == 0) g_cnorm[j] = row_reduce_sq(cs[w]);
}

// ---------------- top-256 by k_dist (desc value, asc index) via bitonic sort ----------------
__global__ void topk_kernel() {
    __shared__ unsigned long long s[LL];
    int bh = blockIdx.x, tid = threadIdx.x;   // 1024 threads
    for (int i = tid; i < LL; i += 1024) {
        float v = g_kdist[(size_t)bh * LL + i];
        unsigned u = __float_as_uint(v);
        u = (u & 0x80000000u) ? ~u : (u | 0x80000000u);  // ascending map
        u = ~u;                                          // descending
        s[i] = ((unsigned long long)u << 32) | (unsigned)i;
    }
    __syncthreads();
    for (int k = 2; k <= LL; k <<= 1) {
        for (int j = k >> 1; j > 0; j >>= 1) {
            for (int i = tid; i < LL; i += 1024) {
                int ixj = i ^ j;
                if (ixj > i) {
                    bool up = ((i & k) == 0);
                    unsigned long long a = s[i], b = s[ixj];
                    if ((a > b) == up) { s[i] = b; s[ixj] = a; }
                }
            }
            __syncthreads();
        }
    }
    if (tid < KCL) g_topk[bh * KCL + tid] = (int)(s[tid] & 0xffffffffu);
}

// ---------------- gather selected k/v ----------------
__global__ void gather_kernel() {
    int idx = blockIdx.x * 256 + threadIdx.x;   // 16*256*32
    int d = idx & 31;
    int r = idx >> 5;           // bh*256 + t
    int bh = r >> 8;
    int src = g_topk[r];
    g_ksel[idx] = g_kt[((size_t)bh * LL + src) * DD + d];
    g_vsel[idx] = g_vt[((size_t)bh * LL + src) * DD + d];
}

// ---------------- attention (online softmax; post-decision, noise-tolerant) ----------------
__global__ void attn_kernel() {
    __shared__ float ks[128 * DD];
    __shared__ float vs[128 * DD];
    int bh = blockIdx.y;
    int b = bh >> 3, h = bh & 7;
    int l = blockIdx.x * 128 + threadIdx.x;

    float q[32];
    const float4* qp = (const float4*)(g_qt + ((size_t)bh * LL + l) * DD);
#pragma unroll
    for (int i = 0; i < 8; i++) ((float4*)q)[i] = qp[i];

    float m = -1e30f, lsum = 0.f;
    float acc[32];
#pragma unroll
    for (int d = 0; d < 32; d++) acc[d] = 0.f;

    for (int c = 0; c < 2; c++) {
        __syncthreads();
        for (int i = threadIdx.x; i < 128 * DD; i += 128) {
            ks[i] = g_ksel[(size_t)bh * KCL * DD + c * 128 * DD + i];
            vs[i] = g_vsel[(size_t)bh * KCL * DD + c * 128 * DD + i];
        }
        __syncthreads();
        for (int j = 0; j < 128; j++) {
            float dot = 0.f;
            const float4* kp = (const float4*)(ks + j * DD);
#pragma unroll
            for (int i = 0; i < 8; i++) {
                float4 k4 = kp[i];
                dot = fmaf(q[i*4+0], k4.x, dot);
                dot = fmaf(q[i*4+1], k4.y, dot);
                dot = fmaf(q[i*4+2], k4.z, dot);
                dot = fmaf(q[i*4+3], k4.w, dot);
            }
            if (dot > m) {
                float corr = expf(m - dot);
                lsum *= corr;
#pragma unroll
                for (int d = 0; d < 32; d++) acc[d] *= corr;
                m = dot;
            }
            float p = expf(dot - m);
            lsum += p;
            const float4* vp = (const float4*)(vs + j * DD);
#pragma unroll
            for (int i = 0; i < 8; i++) {
                float4 v4 = vp[i];
                acc[i*4+0] = fmaf(p, v4.x, acc[i*4+0]);
                acc[i*4+1] = fmaf(p, v4.y, acc[i*4+1]);
                acc[i*4+2] = fmaf(p, v4.z, acc[i*4+2]);
                acc[i*4+3] = fmaf(p, v4.w, acc[i*4+3]);
            }
        }
    }
    float inv = 1.f / lsum;
#pragma unroll
    for (int d = 0; d < 32; d++) {
        g_oin[((size_t)b * CC + h * 32 + d) * LL + l] = acc[d] * inv;
    }
}

// ---------------- final LN + scaled residual (two-pass var, fma squares) ----------------
__global__ void final_kernel(const float* __restrict__ qsrc,
                             const float* __restrict__ gamma,
                             const float* __restrict__ beta,
                             const float* __restrict__ gs,
                             float* __restrict__ out) {
    int n = blockIdx.x * blockDim.x + threadIdx.x;
    int b = n >> 12, l = n & 4095;
    const float* colp = g_o2 + (size_t)b * CC * LL + l;
    float s = 0.f;
    for (int c = 0; c < CC; c++) s = __fadd_rn(s, colp[(size_t)c * LL]);
    float mean = __fdiv_rn(s, 256.f);
    float acc = 0.f;
    for (int c = 0; c < CC; c++) {
        float d = __fsub_rn(colp[(size_t)c * LL], mean);
        acc = fmaf(d, d, acc);
    }
    float var = __fdiv_rn(acc, 256.f);
    float denom = __fadd_rn(sqrtf(var), 1e-6f);
    float g = gs[0];
    for (int c = 0; c < CC; c++) {
        float v = colp[(size_t)c * LL];
        float y = __fadd_rn(__fdiv_rn(__fmul_rn(gamma[c], __fsub_rn(v, mean)), denom), beta[c]);
        out[(size_t)b * CC * LL + (size_t)c * LL + l] =
            fmaf(g, y, qsrc[(size_t)b * CC * LL + (size_t)c * LL + l]);
    }
}

// ---------------- launch ----------------
extern "C" void kernel_launch(void* const* d_in, const int* in_sizes, int n_in,
                              void* d_out, int out_size) {
    const float* qsrc   = (const float*)d_in[0];
    const float* ctx    = (const float*)d_in[1];
    const float* w_q    = (const float*)d_in[2];
    const float* w_kv   = (const float*)d_in[3];
    const float* w_out  = (const float*)d_in[4];
    const float* lnc_g  = (const float*)d_in[5];
    const float* lnc_b  = (const float*)d_in[6];
    const float* lnq_g  = (const float*)d_in[7];
    const float* lnq_b  = (const float*)d_in[8];
    const float* lno_g  = (const float*)d_in[9];
    const float* lno_b  = (const float*)d_in[10];
    const float* gs     = (const float*)d_in[11];
    float* out = (float*)d_out;

    // LN both inputs
    ln_kernel<<<32, 256>>>(ctx,  lnc_g, lnc_b, 0);
    ln_kernel<<<32, 256>>>(qsrc, lnq_g, lnq_b, 1);

    // projections
    gemm_kernel<<<dim3(128, 8), 256>>>(w_kv, 0);   // kv: 512 rows
    gemm_kernel<<<dim3(128, 4), 256>>>(w_q,  1);   // q: 256 rows

    // fold + l2norm + transpose
    fold_kernel<<<dim3(128, NBH), dim3(32, 32)>>>(0);  // q
    fold_kernel<<<dim3(128, NBH), dim3(32, 32)>>>(1);  // k
    fold_kernel<<<dim3(128, NBH), dim3(32, 32)>>>(2);  // v

    // kmeans (deterministic, reference-order arithmetic)
    kinit_kernel<<<KCL, 32>>>();
    for (int it = 0; it < NITER; it++) {
        assign_kernel<<<NPTS / 256, 256>>>(0);
        offset_kernel<<<1, 256>>>();
        scatter_kernel<<<256, 256>>>();
        centroid_kernel<<<32, 256>>>();
    }

    // k assignment + L1 distance to its centroid
    assign_kernel<<<NPTS / 256, 256>>>(1);

    // top-256 per bh, gather
    topk_kernel<<<NBH, 1024>>>();
    gather_kernel<<<NBH * KCL * DD / 256, 256>>>();

    // attention + unfold
    attn_kernel<<<dim3(32, NBH), 128>>>();

    // output projection
    gemm_kernel<<<dim3(128, 4), 256>>>(w_out, 2);

    // final LN + residual
    final_kernel<<<32, 256>>>(qsrc, lno_g, lno_b, gs, out);
}

// round 9
// speedup vs baseline: 1.1961x; 1.0650x over previous
#include <cuda_runtime.h>
#include <math.h>

// Problem dims
#define BB 2
#define CC 256
#define LL 4096
#define HH 8
#define DD 32
#define NBH 16
#define NPTS 65536   // 16*4096
#define KCL 256      // clusters / top_k
#define NITER 10

// ---------------- scratch ----------------
__device__ float g_xc[BB*CC*LL];      // ctx after LN
__device__ float g_xq[BB*CC*LL];      // query_source after LN
__device__ float g_kv[BB*2*CC*LL];    // kv projection
__device__ float g_qp[BB*CC*LL];      // q projection (pre-fold)
__device__ float g_qt[NPTS*DD];       // q  [bh][l][d], l2-normalized
__device__ float g_kt[NPTS*DD];       // k  [bh][l][d], l2-normalized
__device__ float g_vt[NPTS*DD];       // v  [bh][l][d]
__device__ float g_cent[KCL*DD];
__device__ float g_cnorm[KCL];
__device__ int   g_assign[NPTS];
__device__ int   g_bcnt[256*KCL];     // per (virtual 256-pt block) per-cluster counts
__device__ int   g_bstart[256*KCL];   // within-cluster prefix across virtual blocks
__device__ int   g_cbase[KCL];
__device__ int   g_ctot[KCL];
__device__ int   g_list[NPTS];        // per-cluster ordered point lists
__device__ float g_kdist[NPTS];
__device__ int   g_topk[NBH*KCL];
__device__ float g_ksel[NBH*KCL*DD];
__device__ float g_vsel[NBH*KCL*DD];
__device__ float g_oin[BB*CC*LL];     // attention out, unfolded to (b,256,L)
__device__ float g_o2[BB*CC*LL];      // w_out result

// XLA:CPU-style vectorized row reduction over 32 elements:
// 4 lane partial sums, chunks ascending, then (s0+s2)+(s1+s3).
__device__ __forceinline__ float row_reduce_sq(const float* v) {
    float s0 = 0.f, s1 = 0.f, s2 = 0.f, s3 = 0.f;
#pragma unroll
    for (int i = 0; i < 8; i++) {
        s0 = fmaf(v[4*i+0], v[4*i+0], s0);
        s1 = fmaf(v[4*i+1], v[4*i+1], s1);
        s2 = fmaf(v[4*i+2], v[4*i+2], s2);
        s3 = fmaf(v[4*i+3], v[4*i+3], s3);
    }
    return __fadd_rn(__fadd_rn(s0, s2), __fadd_rn(s1, s3));
}

// ---------------- channel layer norm (two-pass var, fma-contracted squares) ----------------
__global__ void ln_kernel(const float* __restrict__ src,
                          const float* __restrict__ gamma,
                          const float* __restrict__ beta, int mode) {
    float* dst = (mode == 0) ? g_xc : g_xq;
    int n = blockIdx.x * blockDim.x + threadIdx.x;   // 0..8191
    int b = n >> 12, l = n & 4095;
    const float* colp = src + (size_t)b * CC * LL + l;
    float s = 0.f;
    for (int c = 0; c < CC; c++) s = __fadd_rn(s, colp[(size_t)c * LL]);
    float mean = __fdiv_rn(s, 256.f);
    float acc = 0.f;
    for (int c = 0; c < CC; c++) {
        float d = __fsub_rn(colp[(size_t)c * LL], mean);
        acc = fmaf(d, d, acc);
    }
    float var = __fdiv_rn(acc, 256.f);
    float denom = __fadd_rn(sqrtf(var), 1e-6f);
    float* dcol = dst + (size_t)b * CC * LL + l;
    for (int c = 0; c < CC; c++) {
        float v = colp[(size_t)c * LL];
        float y = __fadd_rn(__fdiv_rn(__fmul_rn(gamma[c], __fsub_rn(v, mean)), denom), beta[c]);
        dcol[(size_t)c * LL] = y;
    }
}

// ---------------- tiled fp32 GEMM (sequential ascending-k FMA chain per output) ----------------
// Y[b][m][l] = sum_c W[m][c] X[b][c][l]; grid: (8192/64, M/64); block 256; K-tile 32
__global__ void gemm_kernel(const float* __restrict__ W, int mode) {
    const float* X; float* Y; int M;
    if (mode == 0)      { X = g_xc;  Y = g_kv; M = 512; }
    else if (mode == 1) { X = g_xq;  Y = g_qp; M = 256; }
    else                { X = g_oin; Y = g_o2; M = 256; }

    __shared__ float As[32][68];   // padded (mult of 4 for float4 reads)
    __shared__ float Bs[32][64];

    int n0 = blockIdx.x * 64;          // global column (b*4096 + l)
    int m0 = blockIdx.y * 64;
    int b  = n0 >> 12;
    int l0 = n0 & 4095;
    const float* Xb = X + (size_t)b * CC * LL;
    float* Yb = Y + (size_t)b * M * LL;

    int tid = threadIdx.x;
    int tx = tid & 15;   // n micro
    int ty = tid >> 4;   // m micro
    float acc[4][4];
#pragma unroll
    for (int i = 0; i < 4; i++)
#pragma unroll
        for (int j = 0; j < 4; j++) acc[i][j] = 0.f;

    for (int k0 = 0; k0 < CC; k0 += 32) {
#pragma unroll
        for (int idx = tid; idx < 64 * 32; idx += 256) {
            int i = idx >> 5, j = idx & 31;      // i: m, j: k (coalesced along k)
            As[j][i] = W[(size_t)(m0 + i) * CC + k0 + j];
        }
#pragma unroll
        for (int idx = tid; idx < 32 * 64; idx += 256) {
            int i = idx >> 6, j = idx & 63;      // i: k, j: n
            Bs[i][j] = Xb[(size_t)(k0 + i) * LL + l0 + j];
        }
        __syncthreads();
#pragma unroll
        for (int kk = 0; kk < 32; kk++) {
            float a[4], bb[4];
            *(float4*)a  = *(const float4*)&As[kk][ty * 4];
            *(float4*)bb = *(const float4*)&Bs[kk][tx * 4];
#pragma unroll
            for (int i = 0; i < 4; i++)
#pragma unroll
                for (int j = 0; j < 4; j++) acc[i][j] = fmaf(a[i], bb[j], acc[i][j]);
        }
        __syncthreads();
    }
#pragma unroll
    for (int i = 0; i < 4; i++) {
        float4 o = make_float4(acc[i][0], acc[i][1], acc[i][2], acc[i][3]);
        *(float4*)&Yb[(size_t)(m0 + ty * 4 + i) * LL + l0 + tx * 4] = o;
    }
}

// ---------------- fold + optional l2norm + transpose ----------------
__global__ void fold_kernel(int mode) {
    const float* src; float* dst; int rows, off, doNorm;
    if (mode == 0)      { src = g_qp; dst = g_qt; rows = 256; off = 0;   doNorm = 1; }
    else if (mode == 1) { src = g_kv; dst = g_kt; rows = 512; off = 0;   doNorm = 1; }
    else                { src = g_kv; dst = g_vt; rows = 512; off = 256; doNorm = 0; }

    __shared__ float s[32][33];
    __shared__ float nrm[32];
    int bh = blockIdx.y;
    int b = bh >> 3, h = bh & 7;
    int l0 = blockIdx.x * 32;
    int x = threadIdx.x, y = threadIdx.y;   // load: x = l, y = d

    s[y][x] = src[((size_t)b * rows + off + h * 32 + y) * LL + l0 + x];
    __syncthreads();
    if (y == 0) {
        float ss = 0.f;
#pragma unroll
        for (int d = 0; d < 32; d++) { float v = s[d][x]; ss = fmaf(v, v, ss); }
        nrm[x] = fmaxf(sqrtf(ss), 1e-12f);
    }
    __syncthreads();
    // write: x = d, y = l
    float v = s[x][y];
    if (doNorm) v = __fdiv_rn(v, nrm[y]);
    dst[((size_t)bh * LL + l0 + y) * DD + x] = v;
}

// ---------------- kmeans init: centroids = first 256 q rows; VF4-tree cnorm ----------------
__global__ void kinit_kernel() {
    __shared__ float cs[DD];
    int j = blockIdx.x, d = threadIdx.x;
    float v = g_qt[j * DD + d];
    g_cent[j * DD + d] = v;
    cs[d] = v;
    __syncthreads();
    if (d == 0) g_cnorm[j] = row_reduce_sq(cs);
}

// ---------------- assignment, P=2 points/thread ----------------
// p0 = blk*512 + tid, p1 = p0 + 256 : each half is a contiguous 256-point
// virtual block (rows 2*blk, 2*blk+1 of g_bcnt) -> scatter ordering unchanged.
// Per-point float chains bit-identical to R8 (dot = ascending-k FMA, argmin first-min).
__global__ void assign_kernel(int mode) {
    __shared__ float sc[KCL * DD];
    __shared__ float scn[KCL];
    __shared__ int   cnt0[KCL];
    __shared__ int   cnt1[KCL];
    int tid = threadIdx.x;
    for (int i = tid; i < KCL * DD; i += 256) sc[i] = g_cent[i];
    if (tid < KCL) { scn[tid] = g_cnorm[tid]; cnt0[tid] = 0; cnt1[tid] = 0; }
    __syncthreads();

    const float* pts = (mode == 0) ? g_qt : g_kt;
    int p0 = blockIdx.x * 512 + tid;
    int p1 = p0 + 256;

    float x0[32], x1[32];
    const float4* xp0 = (const float4*)(pts + (size_t)p0 * DD);
    const float4* xp1 = (const float4*)(pts + (size_t)p1 * DD);
#pragma unroll
    for (int i = 0; i < 8; i++) { ((float4*)x0)[i] = xp0[i]; ((float4*)x1)[i] = xp1[i]; }
    float xx0 = 0.f, xx1 = 0.f;
#pragma unroll
    for (int d = 0; d < 32; d++) { xx0 = fmaf(x0[d], x0[d], xx0); xx1 = fmaf(x1[d], x1[d], xx1); }

    float best0 = 3.4e38f, best1 = 3.4e38f;
    int bj0 = 0, bj1 = 0;
    for (int j = 0; j < KCL; j += 2) {
        float d00 = 0.f, d01 = 0.f, d10 = 0.f, d11 = 0.f;
        const float4* cpA = (const float4*)(sc + j * DD);
        const float4* cpB = (const float4*)(sc + (j + 1) * DD);
#pragma unroll
        for (int i = 0; i < 8; i++) {
            float4 a4 = cpA[i];
            float4 b4 = cpB[i];
            d00 = fmaf(x0[i*4+0], a4.x, d00);
            d00 = fmaf(x0[i*4+1], a4.y, d00);
            d00 = fmaf(x0[i*4+2], a4.z, d00);
            d00 = fmaf(x0[i*4+3], a4.w, d00);
            d01 = fmaf(x0[i*4+0], b4.x, d01);
            d01 = fmaf(x0[i*4+1], b4.y, d01);
            d01 = fmaf(x0[i*4+2], b4.z, d01);
            d01 = fmaf(x0[i*4+3], b4.w, d01);
            d10 = fmaf(x1[i*4+0], a4.x, d10);
            d10 = fmaf(x1[i*4+1], a4.y, d10);
            d10 = fmaf(x1[i*4+2], a4.z, d10);
            d10 = fmaf(x1[i*4+3], a4.w, d10);
            d11 = fmaf(x1[i*4+0], b4.x, d11);
            d11 = fmaf(x1[i*4+1], b4.y, d11);
            d11 = fmaf(x1[i*4+2], b4.z, d11);
            d11 = fmaf(x1[i*4+3], b4.w, d11);
        }
        float s00 = __fadd_rn(__fsub_rn(xx0, __fmul_rn(2.f, d00)), scn[j]);
        float s01 = __fadd_rn(__fsub_rn(xx0, __fmul_rn(2.f, d01)), scn[j + 1]);
        float s10 = __fadd_rn(__fsub_rn(xx1, __fmul_rn(2.f, d10)), scn[j]);
        float s11 = __fadd_rn(__fsub_rn(xx1, __fmul_rn(2.f, d11)), scn[j + 1]);
        if (s00 < best0) { best0 = s00; bj0 = j; }
        if (s01 < best0) { best0 = s01; bj0 = j + 1; }
        if (s10 < best1) { best1 = s10; bj1 = j; }
        if (s11 < best1) { best1 = s11; bj1 = j + 1; }
    }
    g_assign[p0] = bj0;
    g_assign[p1] = bj1;

    if (mode == 0) {
        int lane = tid & 31;
        unsigned m0 = __match_any_sync(0xffffffffu, bj0);
        if (lane == __ffs(m0) - 1) atomicAdd(&cnt0[bj0], __popc(m0));
        unsigned m1 = __match_any_sync(0xffffffffu, bj1);
        if (lane == __ffs(m1) - 1) atomicAdd(&cnt1[bj1], __popc(m1));
        __syncthreads();
        for (int i = tid; i < KCL; i += 256) {
            g_bcnt[(2 * blockIdx.x)     * KCL + i] = cnt0[i];
            g_bcnt[(2 * blockIdx.x + 1) * KCL + i] = cnt1[i];
        }
    } else {
        // L1 distance: VF4 lane partials (plain adds), (s0+s2)+(s1+s3) tree
        const float* c0 = g_cent + bj0 * DD;
        const float* c1 = g_cent + bj1 * DD;
        float a0 = 0.f, a1 = 0.f, a2 = 0.f, a3 = 0.f;
        float b0 = 0.f, b1 = 0.f, b2 = 0.f, b3 = 0.f;
#pragma unroll
        for (int i = 0; i < 8; i++) {
            a0 = __fadd_rn(a0, fabsf(__fsub_rn(c0[4*i+0], x0[4*i+0])));
            a1 = __fadd_rn(a1, fabsf(__fsub_rn(c0[4*i+1], x0[4*i+1])));
            a2 = __fadd_rn(a2, fabsf(__fsub_rn(c0[4*i+2], x0[4*i+2])));
            a3 = __fadd_rn(a3, fabsf(__fsub_rn(c0[4*i+3], x0[4*i+3])));
            b0 = __fadd_rn(b0, fabsf(__fsub_rn(c1[4*i+0], x1[4*i+0])));
            b1 = __fadd_rn(b1, fabsf(__fsub_rn(c1[4*i+1], x1[4*i+1])));
            b2 = __fadd_rn(b2, fabsf(__fsub_rn(c1[4*i+2], x1[4*i+2])));
            b3 = __fadd_rn(b3, fabsf(__fsub_rn(c1[4*i+3], x1[4*i+3])));
        }
        g_kdist[p0] = __fadd_rn(__fadd_rn(a0, a2), __fadd_rn(a1, a3));
        g_kdist[p1] = __fadd_rn(__fadd_rn(b0, b2), __fadd_rn(b1, b3));
    }
}

// ---------------- offsets: parallel scan (integers, exact) ----------------
__global__ void offset_kernel() {   // 1 block, 256 threads
    __shared__ int wsum[8];
    int j = threadIdx.x;
    int lane = j & 31, w = j >> 5;
    int running = 0;
    for (int b = 0; b < 256; b++) {
        int t = g_bcnt[b * KCL + j];       // coalesced across j
        g_bstart[b * KCL + j] = running;
        running += t;
    }
    int v = running;                        // tot[j]
    int s = v;
#pragma unroll
    for (int o = 1; o < 32; o <<= 1) {
        int n = __shfl_up_sync(0xffffffffu, s, o);
        if (lane >= o) s += n;
    }
    if (lane == 31) wsum[w] = s;
    __syncthreads();
    int woff = 0;
    for (int ww = 0; ww < w; ww++) woff += wsum[ww];
    g_cbase[j] = woff + s - v;
    g_ctot[j]  = v;
}

// ---------------- scatter: parallel, order-preserving (stable ranks) ----------------
__global__ void scatter_kernel() {
    __shared__ int whist[8][KCL];     // per-warp cluster counts -> exclusive prefix
    int tid = threadIdx.x, blk = blockIdx.x;
    int w = tid >> 5, lane = tid & 31;
    for (int i = tid; i < 8 * KCL; i += 256) ((int*)whist)[i] = 0;
    __syncthreads();
    int p = blk * 256 + tid;
    int a = g_assign[p];
    unsigned m = __match_any_sync(0xffffffffu, a);
    int rank = __popc(m & ((1u << lane) - 1u));
    if (lane == __ffs(m) - 1) whist[w][a] = __popc(m);
    __syncthreads();
    int c = tid, s = 0;
#pragma unroll
    for (int ww = 0; ww < 8; ww++) { int t = whist[ww][c]; whist[ww][c] = s; s += t; }
    __syncthreads();
    int pos = g_cbase[a] + g_bstart[blk * KCL + a] + whist[w][a] + rank;
    g_list[pos] = p;
}

// ---------------- centroids: 8 clusters/block, sequential add chain, batch-8 loads ----------------
__global__ void centroid_kernel() {   // grid 32, block 256
    __shared__ float cs[8][DD];
    int w = threadIdx.x >> 5, d = threadIdx.x & 31;
    int j = blockIdx.x * 8 + w;
    int base = g_cbase[j];
    int tot  = g_ctot[j];
    float s = 0.f;
    int i = 0;
    for (; i + 8 <= tot; i += 8) {
        int p0 = g_list[base + i + 0];
        int p1 = g_list[base + i + 1];
        int p2 = g_list[base + i + 2];
        int p3 = g_list[base + i + 3];
        int p4 = g_list[base + i + 4];
        int p5 = g_list[base + i + 5];
        int p6 = g_list[base + i + 6];
        int p7 = g_list[base + i + 7];
        float y0 = g_qt[(size_t)p0 * DD + d];
        float y1 = g_qt[(size_t)p1 * DD + d];
        float y2 = g_qt[(size_t)p2 * DD + d];
        float y3 = g_qt[(size_t)p3 * DD + d];
        float y4 = g_qt[(size_t)p4 * DD + d];
        float y5 = g_qt[(size_t)p5 * DD + d];
        float y6 = g_qt[(size_t)p6 * DD + d];
        float y7 = g_qt[(size_t)p7 * DD + d];
        s = __fadd_rn(s, y0);
        s = __fadd_rn(s, y1);
        s = __fadd_rn(s, y2);
        s = __fadd_rn(s, y3);
        s = __fadd_rn(s, y4);
        s = __fadd_rn(s, y5);
        s = __fadd_rn(s, y6);
        s = __fadd_rn(s, y7);
    }
    for (; i < tot; i++)
        s = __fadd_rn(s, g_qt[(size_t)g_list[base + i] * DD + d]);

    float old = g_cent[j * DD + d];
    float cntf = (float)tot;
    float newc = (tot > 0) ? __fdiv_rn(s, fmaxf(cntf, 1.f)) : old;
    g_cent[j * DD + d] = newc;
    cs[w][d] = newc;
    __syncwarp();
    if (d == 0) g_cnorm[j] = row_reduce_sq(cs[w]);
}

// ---------------- top-256 by k_dist (desc value, asc index) via bitonic sort ----------------
__global__ void topk_kernel() {
    __shared__ unsigned long long s[LL];
    int bh = blockIdx.x, tid = threadIdx.x;   // 1024 threads
    for (int i = tid; i < LL; i += 1024) {
        float v = g_kdist[(size_t)bh * LL + i];
        unsigned u = __float_as_uint(v);
        u = (u & 0x80000000u) ? ~u : (u | 0x80000000u);  // ascending map
        u = ~u;                                          // descending
        s[i] = ((unsigned long long)u << 32) | (unsigned)i;
    }
    __syncthreads();
    for (int k = 2; k <= LL; k <<= 1) {
        for (int j = k >> 1; j > 0; j >>= 1) {
            for (int i = tid; i < LL; i += 1024) {
                int ixj = i ^ j;
                if (ixj > i) {
                    bool up = ((i & k) == 0);
                    unsigned long long a = s[i], b = s[ixj];
                    if ((a > b) == up) { s[i] = b; s[ixj] = a; }
                }
            }
            __syncthreads();
        }
    }
    if (tid < KCL) g_topk[bh * KCL + tid] = (int)(s[tid] & 0xffffffffu);
}

// ---------------- gather selected k/v ----------------
__global__ void gather_kernel() {
    int idx = blockIdx.x * 256 + threadIdx.x;   // 16*256*32
    int d = idx & 31;
    int r = idx >> 5;           // bh*256 + t
    int bh = r >> 8;
    int src = g_topk[r];
    g_ksel[idx] = g_kt[((size_t)bh * LL + src) * DD + d];
    g_vsel[idx] = g_vt[((size_t)bh * LL + src) * DD + d];
}

// ---------------- attention (online softmax; post-decision, noise-tolerant) ----------------
__global__ void attn_kernel() {
    __shared__ float ks[128 * DD];
    __shared__ float vs[128 * DD];
    int bh = blockIdx.y;
    int b = bh >> 3, h = bh & 7;
    int l = blockIdx.x * 128 + threadIdx.x;

    float q[32];
    const float4* qp = (const float4*)(g_qt + ((size_t)bh * LL + l) * DD);
#pragma unroll
    for (int i = 0; i < 8; i++) ((float4*)q)[i] = qp[i];

    float m = -1e30f, lsum = 0.f;
    float acc[32];
#pragma unroll
    for (int d = 0; d < 32; d++) acc[d] = 0.f;

    for (int c = 0; c < 2; c++) {
        __syncthreads();
        for (int i = threadIdx.x; i < 128 * DD; i += 128) {
            ks[i] = g_ksel[(size_t)bh * KCL * DD + c * 128 * DD + i];
            vs[i] = g_vsel[(size_t)bh * KCL * DD + c * 128 * DD + i];
        }
        __syncthreads();
        for (int j = 0; j < 128; j++) {
            float dot = 0.f;
            const float4* kp = (const float4*)(ks + j * DD);
#pragma unroll
            for (int i = 0; i < 8; i++) {
                float4 k4 = kp[i];
                dot = fmaf(q[i*4+0], k4.x, dot);
                dot = fmaf(q[i*4+1], k4.y, dot);
                dot = fmaf(q[i*4+2], k4.z, dot);
                dot = fmaf(q[i*4+3], k4.w, dot);
            }
            if (dot > m) {
                float corr = expf(m - dot);
                lsum *= corr;
#pragma unroll
                for (int d = 0; d < 32; d++) acc[d] *= corr;
                m = dot;
            }
            float p = expf(dot - m);
            lsum += p;
            const float4* vp = (const float4*)(vs + j * DD);
#pragma unroll
            for (int i = 0; i < 8; i++) {
                float4 v4 = vp[i];
                acc[i*4+0] = fmaf(p, v4.x, acc[i*4+0]);
                acc[i*4+1] = fmaf(p, v4.y, acc[i*4+1]);
                acc[i*4+2] = fmaf(p, v4.z, acc[i*4+2]);
                acc[i*4+3] = fmaf(p, v4.w, acc[i*4+3]);
            }
        }
    }
    float inv = 1.f / lsum;
#pragma unroll
    for (int d = 0; d < 32; d++) {
        g_oin[((size_t)b * CC + h * 32 + d) * LL + l] = acc[d] * inv;
    }
}

// ---------------- final LN + scaled residual (two-pass var, fma squares) ----------------
__global__ void final_kernel(const float* __restrict__ qsrc,
                             const float* __restrict__ gamma,
                             const float* __restrict__ beta,
                             const float* __restrict__ gs,
                             float* __restrict__ out) {
    int n = blockIdx.x * blockDim.x + threadIdx.x;
    int b = n >> 12, l = n & 4095;
    const float* colp = g_o2 + (size_t)b * CC * LL + l;
    float s = 0.f;
    for (int c = 0; c < CC; c++) s = __fadd_rn(s, colp[(size_t)c * LL]);
    float mean = __fdiv_rn(s, 256.f);
    float acc = 0.f;
    for (int c = 0; c < CC; c++) {
        float d = __fsub_rn(colp[(size_t)c * LL], mean);
        acc = fmaf(d, d, acc);
    }
    float var = __fdiv_rn(acc, 256.f);
    float denom = __fadd_rn(sqrtf(var), 1e-6f);
    float g = gs[0];
    for (int c = 0; c < CC; c++) {
        float v = colp[(size_t)c * LL];
        float y = __fadd_rn(__fdiv_rn(__fmul_rn(gamma[c], __fsub_rn(v, mean)), denom), beta[c]);
        out[(size_t)b * CC * LL + (size_t)c * LL + l] =
            fmaf(g, y, qsrc[(size_t)b * CC * LL + (size_t)c * LL + l]);
    }
}

// ---------------- launch ----------------
extern "C" void kernel_launch(void* const* d_in, const int* in_sizes, int n_in,
                              void* d_out, int out_size) {
    const float* qsrc   = (const float*)d_in[0];
    const float* ctx    = (const float*)d_in[1];
    const float* w_q    = (const float*)d_in[2];
    const float* w_kv   = (const float*)d_in[3];
    const float* w_out  = (const float*)d_in[4];
    const float* lnc_g  = (const float*)d_in[5];
    const float* lnc_b  = (const float*)d_in[6];
    const float* lnq_g  = (const float*)d_in[7];
    const float* lnq_b  = (const float*)d_in[8];
    const float* lno_g  = (const float*)d_in[9];
    const float* lno_b  = (const float*)d_in[10];
    const float* gs     = (const float*)d_in[11];
    float* out = (float*)d_out;

    // LN both inputs
    ln_kernel<<<32, 256>>>(ctx,  lnc_g, lnc_b, 0);
    ln_kernel<<<32, 256>>>(qsrc, lnq_g, lnq_b, 1);

    // projections
    gemm_kernel<<<dim3(128, 8), 256>>>(w_kv, 0);   // kv: 512 rows
    gemm_kernel<<<dim3(128, 4), 256>>>(w_q,  1);   // q: 256 rows

    // fold + l2norm + transpose
    fold_kernel<<<dim3(128, NBH), dim3(32, 32)>>>(0);  // q
    fold_kernel<<<dim3(128, NBH), dim3(32, 32)>>>(1);  // k
    fold_kernel<<<dim3(128, NBH), dim3(32, 32)>>>(2);  // v

    // kmeans (deterministic, reference-order arithmetic)
    kinit_kernel<<<KCL, 32>>>();
    for (int it = 0; it < NITER; it++) {
        assign_kernel<<<NPTS / 512, 256>>>(0);
        offset_kernel<<<1, 256>>>();
        scatter_kernel<<<256, 256>>>();
        centroid_kernel<<<32, 256>>>();
    }

    // k assignment + L1 distance to its centroid
    assign_kernel<<<NPTS / 512, 256>>>(1);

    // top-256 per bh, gather
    topk_kernel<<<NBH, 1024>>>();
    gather_kernel<<<NBH * KCL * DD / 256, 256>>>();

    // attention + unfold
    attn_kernel<<<dim3(32, NBH), 128>>>();

    // output projection
    gemm_kernel<<<dim3(128, 4), 256>>>(w_out, 2);

    // final LN + residual
    final_kernel<<<32, 256>>>(qsrc, lno_g, lno_b, gs, out);
}

// round 10
// speedup vs baseline: 1.3124x; 1.0973x over previous
#include <cuda_runtime.h>
#include <math.h>

// Problem dims
#define BB 2
#define CC 256
#define LL 4096
#define HH 8
#define DD 32
#define NBH 16
#define NPTS 65536   // 16*4096
#define KCL 256      // clusters / top_k
#define NITER 10

typedef unsigned long long ull;

// ---- packed fp32x2 helpers (per-lane IEEE rn; bit-identical to scalar ops) ----
__device__ __forceinline__ ull pk2(float lo, float hi) {
    ull r; asm("mov.b64 %0, {%1, %2};" : "=l"(r) : "f"(lo), "f"(hi)); return r;
}
__device__ __forceinline__ void upk2(ull v, float& lo, float& hi) {
    asm("mov.b64 {%0, %1}, %2;" : "=f"(lo), "=f"(hi) : "l"(v));
}
__device__ __forceinline__ ull fma2(ull a, ull b, ull c) {
    ull d; asm("fma.rn.f32x2 %0, %1, %2, %3;" : "=l"(d) : "l"(a), "l"(b), "l"(c)); return d;
}
__device__ __forceinline__ ull mul2(ull a, ull b) {
    ull d; asm("mul.rn.f32x2 %0, %1, %2;" : "=l"(d) : "l"(a), "l"(b)); return d;
}

// ---------------- scratch ----------------
__device__ float g_xc[BB*CC*LL];      // ctx after LN
__device__ float g_xq[BB*CC*LL];      // query_source after LN
__device__ float g_kv[BB*2*CC*LL];    // kv projection
__device__ float g_qp[BB*CC*LL];      // q projection (pre-fold)
__device__ float g_qt[NPTS*DD];       // q  [bh][l][d], l2-normalized
__device__ float g_kt[NPTS*DD];       // k  [bh][l][d], l2-normalized
__device__ float g_vt[NPTS*DD];       // v  [bh][l][d]
__device__ float g_cent[KCL*DD];
__device__ float g_cnorm[KCL];
__device__ int   g_assign[NPTS];
__device__ int   g_bcnt[KCL*256];     // TRANSPOSED: [cluster][block]
__device__ int   g_bstart[KCL*256];   // TRANSPOSED: [cluster][block] within-cluster prefix
__device__ int   g_cbase[KCL];
__device__ int   g_ctot[KCL];
__device__ int   g_list[NPTS];        // per-cluster ordered point lists
__device__ float g_kdist[NPTS];
__device__ int   g_topk[NBH*KCL];
__device__ float g_ksel[NBH*KCL*DD];
__device__ float g_vsel[NBH*KCL*DD];
__device__ float g_oin[BB*CC*LL];     // attention out, unfolded to (b,256,L)
__device__ float g_o2[BB*CC*LL];      // w_out result

// XLA:CPU-style vectorized row reduction over 32 elements:
// 4 lane partial sums, chunks ascending, then (s0+s2)+(s1+s3).
__device__ __forceinline__ float row_reduce_sq(const float* v) {
    float s0 = 0.f, s1 = 0.f, s2 = 0.f, s3 = 0.f;
#pragma unroll
    for (int i = 0; i < 8; i++) {
        s0 = fmaf(v[4*i+0], v[4*i+0], s0);
        s1 = fmaf(v[4*i+1], v[4*i+1], s1);
        s2 = fmaf(v[4*i+2], v[4*i+2], s2);
        s3 = fmaf(v[4*i+3], v[4*i+3], s3);
    }
    return __fadd_rn(__fadd_rn(s0, s2), __fadd_rn(s1, s3));
}

// ---------------- channel layer norm (two-pass var, fma-contracted squares) ----------------
__global__ void ln_kernel(const float* __restrict__ src,
                          const float* __restrict__ gamma,
                          const float* __restrict__ beta, int mode) {
    float* dst = (mode == 0) ? g_xc : g_xq;
    int n = blockIdx.x * blockDim.x + threadIdx.x;   // 0..8191
    int b = n >> 12, l = n & 4095;
    const float* colp = src + (size_t)b * CC * LL + l;
    float s = 0.f;
    for (int c = 0; c < CC; c++) s = __fadd_rn(s, colp[(size_t)c * LL]);
    float mean = __fdiv_rn(s, 256.f);
    float acc = 0.f;
    for (int c = 0; c < CC; c++) {
        float d = __fsub_rn(colp[(size_t)c * LL], mean);
        acc = fmaf(d, d, acc);
    }
    float var = __fdiv_rn(acc, 256.f);
    float denom = __fadd_rn(sqrtf(var), 1e-6f);
    float* dcol = dst + (size_t)b * CC * LL + l;
    for (int c = 0; c < CC; c++) {
        float v = colp[(size_t)c * LL];
        float y = __fadd_rn(__fdiv_rn(__fmul_rn(gamma[c], __fsub_rn(v, mean)), denom), beta[c]);
        dcol[(size_t)c * LL] = y;
    }
}

// ---------------- tiled fp32 GEMM (K16, f32x2-packed output pairs) ----------------
// Y[b][m][l] = sum_c W[m][c] X[b][c][l]; per-output chain = ascending-k FMA (bit-frozen)
__global__ void gemm_kernel(const float* __restrict__ W, int mode) {
    const float* X; float* Y; int M;
    if (mode == 0)      { X = g_xc;  Y = g_kv; M = 512; }
    else if (mode == 1) { X = g_xq;  Y = g_qp; M = 256; }
    else                { X = g_oin; Y = g_o2; M = 256; }

    __shared__ float As[16][68];   // padded: kills bank conflict on fill
    __shared__ float Bs[16][64];

    int n0 = blockIdx.x * 64;          // global column (b*4096 + l)
    int m0 = blockIdx.y * 64;
    int b  = n0 >> 12;
    int l0 = n0 & 4095;
    const float* Xb = X + (size_t)b * CC * LL;
    float* Yb = Y + (size_t)b * M * LL;

    int tid = threadIdx.x;
    int tx = tid & 15;   // n micro
    int ty = tid >> 4;   // m micro
    ull acc01[4], acc23[4];
#pragma unroll
    for (int i = 0; i < 4; i++) { acc01[i] = pk2(0.f, 0.f); acc23[i] = pk2(0.f, 0.f); }

    for (int k0 = 0; k0 < CC; k0 += 16) {
#pragma unroll
        for (int idx = tid; idx < 64 * 16; idx += 256) {
            int i = idx >> 4, j = idx & 15;      // i: m, j: k
            As[j][i] = W[(size_t)(m0 + i) * CC + k0 + j];
        }
#pragma unroll
        for (int idx = tid; idx < 16 * 64; idx += 256) {
            int i = idx >> 6, j = idx & 63;      // i: k, j: n
            Bs[i][j] = Xb[(size_t)(k0 + i) * LL + l0 + j];
        }
        __syncthreads();
#pragma unroll
        for (int kk = 0; kk < 16; kk++) {
            float a[4];
            *(float4*)a = *(const float4*)&As[kk][ty * 4];
            ull b01 = *(const ull*)&Bs[kk][tx * 4];
            ull b23 = *(const ull*)&Bs[kk][tx * 4 + 2];
#pragma unroll
            for (int i = 0; i < 4; i++) {
                ull ap = pk2(a[i], a[i]);
                acc01[i] = fma2(ap, b01, acc01[i]);
                acc23[i] = fma2(ap, b23, acc23[i]);
            }
        }
        __syncthreads();
    }
#pragma unroll
    for (int i = 0; i < 4; i++) {
        float o0, o1, o2, o3;
        upk2(acc01[i], o0, o1);
        upk2(acc23[i], o2, o3);
        float4 o = make_float4(o0, o1, o2, o3);
        *(float4*)&Yb[(size_t)(m0 + ty * 4 + i) * LL + l0 + tx * 4] = o;
    }
}

// ---------------- fold + optional l2norm + transpose ----------------
__global__ void fold_kernel(int mode) {
    const float* src; float* dst; int rows, off, doNorm;
    if (mode == 0)      { src = g_qp; dst = g_qt; rows = 256; off = 0;   doNorm = 1; }
    else if (mode == 1) { src = g_kv; dst = g_kt; rows = 512; off = 0;   doNorm = 1; }
    else                { src = g_kv; dst = g_vt; rows = 512; off = 256; doNorm = 0; }

    __shared__ float s[32][33];
    __shared__ float nrm[32];
    int bh = blockIdx.y;
    int b = bh >> 3, h = bh & 7;
    int l0 = blockIdx.x * 32;
    int x = threadIdx.x, y = threadIdx.y;   // load: x = l, y = d

    s[y][x] = src[((size_t)b * rows + off + h * 32 + y) * LL + l0 + x];
    __syncthreads();
    if (y == 0) {
        float ss = 0.f;
#pragma unroll
        for (int d = 0; d < 32; d++) { float v = s[d][x]; ss = fmaf(v, v, ss); }
        nrm[x] = fmaxf(sqrtf(ss), 1e-12f);
    }
    __syncthreads();
    // write: x = d, y = l
    float v = s[x][y];
    if (doNorm) v = __fdiv_rn(v, nrm[y]);
    dst[((size_t)bh * LL + l0 + y) * DD + x] = v;
}

// ---------------- kmeans init: centroids = first 256 q rows; VF4-tree cnorm ----------------
__global__ void kinit_kernel() {
    __shared__ float cs[DD];
    int j = blockIdx.x, d = threadIdx.x;
    float v = g_qt[j * DD + d];
    g_cent[j * DD + d] = v;
    cs[d] = v;
    __syncthreads();
    if (d == 0) g_cnorm[j] = row_reduce_sq(cs);
}

// ---------------- assignment: P=1/thread, f32x2-packed cluster pairs ----------------
// Each packed lane carries one cluster's dot chain in ascending-k FMA order (bit-frozen).
// Clusters evaluated 4 at a time via two packed chains; argmin checked in ascending order.
__global__ void __launch_bounds__(256) assign_kernel(int mode) {
    __shared__ float2 sc2[(KCL/2) * DD];   // sc2[jp*DD+k] = (cent[2jp][k], cent[2jp+1][k])
    __shared__ float scn[KCL];
    __shared__ int   cnt[KCL];
    int tid = threadIdx.x;
    for (int i = tid; i < (KCL/2) * DD; i += 256) {
        int jp = i >> 5, k = i & 31;
        sc2[i] = make_float2(g_cent[(2*jp) * DD + k], g_cent[(2*jp+1) * DD + k]);
    }
    if (tid < KCL) { scn[tid] = g_cnorm[tid]; cnt[tid] = 0; }
    __syncthreads();

    const float* pts = (mode == 0) ? g_qt : g_kt;
    int p = blockIdx.x * 256 + tid;

    float x[32];
    const float4* xp = (const float4*)(pts + (size_t)p * DD);
#pragma unroll
    for (int i = 0; i < 8; i++) ((float4*)x)[i] = xp[i];
    float xx = 0.f;
#pragma unroll
    for (int d = 0; d < 32; d++) xx = fmaf(x[d], x[d], xx);
    ull xb[32];
#pragma unroll
    for (int d = 0; d < 32; d++) xb[d] = pk2(x[d], x[d]);

    float best = 3.4e38f; int bj = 0;
    for (int j4 = 0; j4 < KCL; j4 += 4) {
        int jp = j4 >> 1;
        ull dA = pk2(0.f, 0.f), dB = pk2(0.f, 0.f);
        const ull* cA = (const ull*)(sc2 + jp * DD);
        const ull* cB = (const ull*)(sc2 + (jp + 1) * DD);
#pragma unroll
        for (int k = 0; k < 32; k++) {
            dA = fma2(xb[k], cA[k], dA);
            dB = fma2(xb[k], cB[k], dB);
        }
        float d0, d1, d2, d3;
        upk2(dA, d0, d1);
        upk2(dB, d2, d3);
        float s0 = __fadd_rn(__fsub_rn(xx, __fmul_rn(2.f, d0)), scn[j4]);
        float s1 = __fadd_rn(__fsub_rn(xx, __fmul_rn(2.f, d1)), scn[j4 + 1]);
        float s2 = __fadd_rn(__fsub_rn(xx, __fmul_rn(2.f, d2)), scn[j4 + 2]);
        float s3 = __fadd_rn(__fsub_rn(xx, __fmul_rn(2.f, d3)), scn[j4 + 3]);
        if (s0 < best) { best = s0; bj = j4; }
        if (s1 < best) { best = s1; bj = j4 + 1; }
        if (s2 < best) { best = s2; bj = j4 + 2; }
        if (s3 < best) { best = s3; bj = j4 + 3; }
    }
    g_assign[p] = bj;

    if (mode == 0) {
        int lane = tid & 31;
        unsigned m = __match_any_sync(0xffffffffu, bj);
        if (lane == __ffs(m) - 1) atomicAdd(&cnt[bj], __popc(m));
        __syncthreads();
        for (int i = tid; i < KCL; i += 256)
            g_bcnt[i * 256 + blockIdx.x] = cnt[i];       // transposed
    } else {
        // L1 distance: VF4 lane partials (plain adds), (s0+s2)+(s1+s3) tree (bit-frozen)
        const float* xo = pts + (size_t)p * DD;
        const float* co = g_cent + bj * DD;
        float a0 = 0.f, a1 = 0.f, a2 = 0.f, a3 = 0.f;
#pragma unroll
        for (int i = 0; i < 8; i++) {
            a0 = __fadd_rn(a0, fabsf(__fsub_rn(co[4*i+0], xo[4*i+0])));
            a1 = __fadd_rn(a1, fabsf(__fsub_rn(co[4*i+1], xo[4*i+1])));
            a2 = __fadd_rn(a2, fabsf(__fsub_rn(co[4*i+2], xo[4*i+2])));
            a3 = __fadd_rn(a3, fabsf(__fsub_rn(co[4*i+3], xo[4*i+3])));
        }
        g_kdist[p] = __fadd_rn(__fadd_rn(a0, a2), __fadd_rn(a1, a3));
    }
}

// ---------------- per-cluster scan over blocks (parallel; integers, exact) ----------------
__global__ void scan_kernel() {   // 256 blocks (one per cluster), 256 threads
    __shared__ int wsum[8];
    int j = blockIdx.x, b = threadIdx.x;
    int lane = b & 31, w = b >> 5;
    int v = g_bcnt[j * 256 + b];           // coalesced (transposed layout)
    int s = v;
#pragma unroll
    for (int o = 1; o < 32; o <<= 1) {
        int n = __shfl_up_sync(0xffffffffu, s, o);
        if (lane >= o) s += n;
    }
    if (lane == 31) wsum[w] = s;
    __syncthreads();
    int woff = 0;
    for (int ww = 0; ww < w; ww++) woff += wsum[ww];
    int excl = woff + s - v;
    g_bstart[j * 256 + b] = excl;
    if (b == 255) g_ctot[j] = excl + v;
}

// ---------------- cluster bases: tiny exclusive scan of totals ----------------
__global__ void cbase_kernel() {   // 1 block, 256 threads
    __shared__ int wsum[8];
    int j = threadIdx.x;
    int lane = j & 31, w = j >> 5;
    int v = g_ctot[j];
    int s = v;
#pragma unroll
    for (int o = 1; o < 32; o <<= 1) {
        int n = __shfl_up_sync(0xffffffffu, s, o);
        if (lane >= o) s += n;
    }
    if (lane == 31) wsum[w] = s;
    __syncthreads();
    int woff = 0;
    for (int ww = 0; ww < w; ww++) woff += wsum[ww];
    g_cbase[j] = woff + s - v;
}

// ---------------- scatter: parallel, order-preserving (stable ranks) ----------------
__global__ void scatter_kernel() {
    __shared__ int whist[8][KCL];     // per-warp cluster counts -> exclusive prefix
    int tid = threadIdx.x, blk = blockIdx.x;
    int w = tid >> 5, lane = tid & 31;
    for (int i = tid; i < 8 * KCL; i += 256) ((int*)whist)[i] = 0;
    __syncthreads();
    int p = blk * 256 + tid;
    int a = g_assign[p];
    unsigned m = __match_any_sync(0xffffffffu, a);
    int rank = __popc(m & ((1u << lane) - 1u));
    if (lane == __ffs(m) - 1) whist[w][a] = __popc(m);
    __syncthreads();
    int c = tid, s = 0;
#pragma unroll
    for (int ww = 0; ww < 8; ww++) { int t = whist[ww][c]; whist[ww][c] = s; s += t; }
    __syncthreads();
    int pos = g_cbase[a] + g_bstart[a * 256 + blk] + whist[w][a] + rank;
    g_list[pos] = p;
}

// ---------------- centroids: 8 clusters/block, sequential add chain, batch-8 loads ----------------
__global__ void centroid_kernel() {   // grid 32, block 256
    __shared__ float cs[8][DD];
    int w = threadIdx.x >> 5, d = threadIdx.x & 31;
    int j = blockIdx.x * 8 + w;
    int base = g_cbase[j];
    int tot  = g_ctot[j];
    float s = 0.f;
    int i = 0;
    for (; i + 8 <= tot; i += 8) {
        int p0 = g_list[base + i + 0];
        int p1 = g_list[base + i + 1];
        int p2 = g_list[base + i + 2];
        int p3 = g_list[base + i + 3];
        int p4 = g_list[base + i + 4];
        int p5 = g_list[base + i + 5];
        int p6 = g_list[base + i + 6];
        int p7 = g_list[base + i + 7];
        float y0 = g_qt[(size_t)p0 * DD + d];
        float y1 = g_qt[(size_t)p1 * DD + d];
        float y2 = g_qt[(size_t)p2 * DD + d];
        float y3 = g_qt[(size_t)p3 * DD + d];
        float y4 = g_qt[(size_t)p4 * DD + d];
        float y5 = g_qt[(size_t)p5 * DD + d];
        float y6 = g_qt[(size_t)p6 * DD + d];
        float y7 = g_qt[(size_t)p7 * DD + d];
        s = __fadd_rn(s, y0);
        s = __fadd_rn(s, y1);
        s = __fadd_rn(s, y2);
        s = __fadd_rn(s, y3);
        s = __fadd_rn(s, y4);
        s = __fadd_rn(s, y5);
        s = __fadd_rn(s, y6);
        s = __fadd_rn(s, y7);
    }
    for (; i < tot; i++)
        s = __fadd_rn(s, g_qt[(size_t)g_list[base + i] * DD + d]);

    float old = g_cent[j * DD + d];
    float cntf = (float)tot;
    float newc = (tot > 0) ? __fdiv_rn(s, fmaxf(cntf, 1.f)) : old;
    g_cent[j * DD + d] = newc;
    cs[w][d] = newc;
    __syncwarp();
    if (d == 0) g_cnorm[j] = row_reduce_sq(cs[w]);
}

// ---------------- top-256 by k_dist (desc value, asc index) via bitonic sort ----------------
__global__ void topk_kernel() {
    __shared__ unsigned long long s[LL];
    int bh = blockIdx.x, tid = threadIdx.x;   // 1024 threads
    for (int i = tid; i < LL; i += 1024) {
        float v = g_kdist[(size_t)bh * LL + i];
        unsigned u = __float_as_uint(v);
        u = (u & 0x80000000u) ? ~u : (u | 0x80000000u);  // ascending map
        u = ~u;                                          // descending
        s[i] = ((unsigned long long)u << 32) | (unsigned)i;
    }
    __syncthreads();
    for (int k = 2; k <= LL; k <<= 1) {
        for (int j = k >> 1; j > 0; j >>= 1) {
            for (int i = tid; i < LL; i += 1024) {
                int ixj = i ^ j;
                if (ixj > i) {
                    bool up = ((i & k) == 0);
                    unsigned long long a = s[i], b = s[ixj];
                    if ((a > b) == up) { s[i] = b; s[ixj] = a; }
                }
            }
            __syncthreads();
        }
    }
    if (tid < KCL) g_topk[bh * KCL + tid] = (int)(s[tid] & 0xffffffffu);
}

// ---------------- gather selected k/v ----------------
__global__ void gather_kernel() {
    int idx = blockIdx.x * 256 + threadIdx.x;   // 16*256*32
    int d = idx & 31;
    int r = idx >> 5;           // bh*256 + t
    int bh = r >> 8;
    int src = g_topk[r];
    g_ksel[idx] = g_kt[((size_t)bh * LL + src) * DD + d];
    g_vsel[idx] = g_vt[((size_t)bh * LL + src) * DD + d];
}

// ---------------- attention (online softmax; acc packed across d — bit-identical) ----------------
__global__ void attn_kernel() {
    __shared__ float ks[128 * DD];
    __shared__ float vs[128 * DD];
    int bh = blockIdx.y;
    int b = bh >> 3, h = bh & 7;
    int l = blockIdx.x * 128 + threadIdx.x;

    float q[32];
    const float4* qp = (const float4*)(g_qt + ((size_t)bh * LL + l) * DD);
#pragma unroll
    for (int i = 0; i < 8; i++) ((float4*)q)[i] = qp[i];

    float m = -1e30f, lsum = 0.f;
    ull accp[16];
#pragma unroll
    for (int d2 = 0; d2 < 16; d2++) accp[d2] = pk2(0.f, 0.f);

    for (int c = 0; c < 2; c++) {
        __syncthreads();
        for (int i = threadIdx.x; i < 128 * DD; i += 128) {
            ks[i] = g_ksel[(size_t)bh * KCL * DD + c * 128 * DD + i];
            vs[i] = g_vsel[(size_t)bh * KCL * DD + c * 128 * DD + i];
        }
        __syncthreads();
        for (int j = 0; j < 128; j++) {
            float dot = 0.f;
            const float4* kp = (const float4*)(ks + j * DD);
#pragma unroll
            for (int i = 0; i < 8; i++) {
                float4 k4 = kp[i];
                dot = fmaf(q[i*4+0], k4.x, dot);
                dot = fmaf(q[i*4+1], k4.y, dot);
                dot = fmaf(q[i*4+2], k4.z, dot);
                dot = fmaf(q[i*4+3], k4.w, dot);
            }
            if (dot > m) {
                float corr = expf(m - dot);
                lsum *= corr;
                ull cc = pk2(corr, corr);
#pragma unroll
                for (int d2 = 0; d2 < 16; d2++) accp[d2] = mul2(accp[d2], cc);
                m = dot;
            }
            float p = expf(dot - m);
            lsum += p;
            ull pp = pk2(p, p);
            const ull* vp = (const ull*)(vs + j * DD);
#pragma unroll
            for (int d2 = 0; d2 < 16; d2++) accp[d2] = fma2(pp, vp[d2], accp[d2]);
        }
    }
    float inv = 1.f / lsum;
#pragma unroll
    for (int d2 = 0; d2 < 16; d2++) {
        float a0, a1;
        upk2(accp[d2], a0, a1);
        g_oin[((size_t)b * CC + h * 32 + 2*d2)     * LL + l] = a0 * inv;
        g_oin[((size_t)b * CC + h * 32 + 2*d2 + 1) * LL + l] = a1 * inv;
    }
}

// ---------------- final LN + scaled residual (two-pass var, fma squares) ----------------
__global__ void final_kernel(const float* __restrict__ qsrc,
                             const float* __restrict__ gamma,
                             const float* __restrict__ beta,
                             const float* __restrict__ gs,
                             float* __restrict__ out) {
    int n = blockIdx.x * blockDim.x + threadIdx.x;
    int b = n >> 12, l = n & 4095;
    const float* colp = g_o2 + (size_t)b * CC * LL + l;
    float s = 0.f;
    for (int c = 0; c < CC; c++) s = __fadd_rn(s, colp[(size_t)c * LL]);
    float mean = __fdiv_rn(s, 256.f);
    float acc = 0.f;
    for (int c = 0; c < CC; c++) {
        float d = __fsub_rn(colp[(size_t)c * LL], mean);
        acc = fmaf(d, d, acc);
    }
    float var = __fdiv_rn(acc, 256.f);
    float denom = __fadd_rn(sqrtf(var), 1e-6f);
    float g = gs[0];
    for (int c = 0; c < CC; c++) {
        float v = colp[(size_t)c * LL];
        float y = __fadd_rn(__fdiv_rn(__fmul_rn(gamma[c], __fsub_rn(v, mean)), denom), beta[c]);
        out[(size_t)b * CC * LL + (size_t)c * LL + l] =
            fmaf(g, y, qsrc[(size_t)b * CC * LL + (size_t)c * LL + l]);
    }
}

// ---------------- launch ----------------
extern "C" void kernel_launch(void* const* d_in, const int* in_sizes, int n_in,
                              void* d_out, int out_size) {
    const float* qsrc   = (const float*)d_in[0];
    const float* ctx    = (const float*)d_in[1];
    const float* w_q    = (const float*)d_in[2];
    const float* w_kv   = (const float*)d_in[3];
    const float* w_out  = (const float*)d_in[4];
    const float* lnc_g  = (const float*)d_in[5];
    const float* lnc_b  = (const float*)d_in[6];
    const float* lnq_g  = (const float*)d_in[7];
    const float* lnq_b  = (const float*)d_in[8];
    const float* lno_g  = (const float*)d_in[9];
    const float* lno_b  = (const float*)d_in[10];
    const float* gs     = (const float*)d_in[11];
    float* out = (float*)d_out;

    // LN both inputs
    ln_kernel<<<32, 256>>>(ctx,  lnc_g, lnc_b, 0);
    ln_kernel<<<32, 256>>>(qsrc, lnq_g, lnq_b, 1);

    // projections
    gemm_kernel<<<dim3(128, 8), 256>>>(w_kv, 0);   // kv: 512 rows
    gemm_kernel<<<dim3(128, 4), 256>>>(w_q,  1);   // q: 256 rows

    // fold + l2norm + transpose
    fold_kernel<<<dim3(128, NBH), dim3(32, 32)>>>(0);  // q
    fold_kernel<<<dim3(128, NBH), dim3(32, 32)>>>(1);  // k
    fold_kernel<<<dim3(128, NBH), dim3(32, 32)>>>(2);  // v

    // kmeans (deterministic, reference-order arithmetic)
    kinit_kernel<<<KCL, 32>>>();
    for (int it = 0; it < NITER; it++) {
        assign_kernel<<<256, 256>>>(0);
        scan_kernel<<<256, 256>>>();
        cbase_kernel<<<1, 256>>>();
        scatter_kernel<<<256, 256>>>();
        centroid_kernel<<<32, 256>>>();
    }

    // k assignment + L1 distance to its centroid
    assign_kernel<<<256, 256>>>(1);

    // top-256 per bh, gather
    topk_kernel<<<NBH, 1024>>>();
    gather_kernel<<<NBH * KCL * DD / 256, 256>>>();

    // attention + unfold
    attn_kernel<<<dim3(32, NBH), 128>>>();

    // output projection
    gemm_kernel<<<dim3(128, 4), 256>>>(w_out, 2);

    // final LN + residual
    final_kernel<<<32, 256>>>(qsrc, lno_g, lno_b, gs, out);
}

// round 11
// speedup vs baseline: 1.5625x; 1.1906x over previous
#include <cuda_runtime.h>
#include <math.h>

// Problem dims
#define BB 2
#define CC 256
#define LL 4096
#define HH 8
#define DD 32
#define NBH 16
#define NPTS 65536   // 16*4096
#define KCL 256      // clusters / top_k
#define NITER 10

typedef unsigned long long ull;

// ---- packed fp32x2 helpers (per-lane IEEE rn; bit-identical to scalar ops) ----
__device__ __forceinline__ ull pk2(float lo, float hi) {
    ull r; asm("mov.b64 %0, {%1, %2};" : "=l"(r) : "f"(lo), "f"(hi)); return r;
}
__device__ __forceinline__ void upk2(ull v, float& lo, float& hi) {
    asm("mov.b64 {%0, %1}, %2;" : "=f"(lo), "=f"(hi) : "l"(v));
}
__device__ __forceinline__ ull fma2(ull a, ull b, ull c) {
    ull d; asm("fma.rn.f32x2 %0, %1, %2, %3;" : "=l"(d) : "l"(a), "l"(b), "l"(c)); return d;
}
__device__ __forceinline__ ull mul2(ull a, ull b) {
    ull d; asm("mul.rn.f32x2 %0, %1, %2;" : "=l"(d) : "l"(a), "l"(b)); return d;
}

// ---------------- scratch ----------------
__device__ float g_xc[BB*CC*LL];      // ctx after LN
__device__ float g_xq[BB*CC*LL];      // query_source after LN
__device__ float g_kv[BB*2*CC*LL];    // kv projection
__device__ float g_qp[BB*CC*LL];      // q projection (pre-fold)
__device__ float g_qt[NPTS*DD];       // q  [bh][l][d], l2-normalized
__device__ float g_kt[NPTS*DD];       // k  [bh][l][d], l2-normalized
__device__ float g_vt[NPTS*DD];       // v  [bh][l][d]
__device__ float g_cent[KCL*DD];
__device__ float g_cnorm[KCL];
__device__ int   g_assign[NPTS];
__device__ int   g_bcnt[KCL*256];     // TRANSPOSED: [cluster][block]
__device__ int   g_bstart[KCL*256];   // TRANSPOSED: [cluster][block] within-cluster prefix
__device__ int   g_ctot[KCL];
__device__ int   g_list[NPTS];        // per-cluster ordered point lists
__device__ float g_kdist[NPTS];
__device__ int   g_topk[NBH*KCL];
__device__ float g_ksel[NBH*KCL*DD];
__device__ float g_vsel[NBH*KCL*DD];
__device__ float g_oin[BB*CC*LL];     // attention out, unfolded to (b,256,L)
__device__ float g_o2[BB*CC*LL];      // w_out result

// XLA:CPU-style vectorized row reduction over 32 elements:
// 4 lane partial sums, chunks ascending, then (s0+s2)+(s1+s3).
__device__ __forceinline__ float row_reduce_sq(const float* v) {
    float s0 = 0.f, s1 = 0.f, s2 = 0.f, s3 = 0.f;
#pragma unroll
    for (int i = 0; i < 8; i++) {
        s0 = fmaf(v[4*i+0], v[4*i+0], s0);
        s1 = fmaf(v[4*i+1], v[4*i+1], s1);
        s2 = fmaf(v[4*i+2], v[4*i+2], s2);
        s3 = fmaf(v[4*i+3], v[4*i+3], s3);
    }
    return __fadd_rn(__fadd_rn(s0, s2), __fadd_rn(s1, s3));
}

// block-wide exclusive prefix over 256 ints held one-per-thread; result via shared
__device__ __forceinline__ int block_excl_scan_256(int v, int* wsum /*>=8*/) {
    int lane = threadIdx.x & 31, w = threadIdx.x >> 5;
    int s = v;
#pragma unroll
    for (int o = 1; o < 32; o <<= 1) {
        int n = __shfl_up_sync(0xffffffffu, s, o);
        if (lane >= o) s += n;
    }
    if (lane == 31) wsum[w] = s;
    __syncthreads();
    int woff = 0;
    for (int ww = 0; ww < w; ww++) woff += wsum[ww];
    return woff + s - v;
}

// ---------------- channel layer norm (two-pass var; MLP-8 batched loads, chain frozen) ----------------
__global__ void ln_kernel(const float* __restrict__ src,
                          const float* __restrict__ gamma,
                          const float* __restrict__ beta, int mode) {
    float* dst = (mode == 0) ? g_xc : g_xq;
    int n = blockIdx.x * blockDim.x + threadIdx.x;   // 0..8191
    int b = n >> 12, l = n & 4095;
    const float* colp = src + (size_t)b * CC * LL + l;
    float s = 0.f;
    for (int c = 0; c < CC; c += 8) {
        float y0 = colp[(size_t)(c+0) * LL], y1 = colp[(size_t)(c+1) * LL];
        float y2 = colp[(size_t)(c+2) * LL], y3 = colp[(size_t)(c+3) * LL];
        float y4 = colp[(size_t)(c+4) * LL], y5 = colp[(size_t)(c+5) * LL];
        float y6 = colp[(size_t)(c+6) * LL], y7 = colp[(size_t)(c+7) * LL];
        s = __fadd_rn(s, y0); s = __fadd_rn(s, y1);
        s = __fadd_rn(s, y2); s = __fadd_rn(s, y3);
        s = __fadd_rn(s, y4); s = __fadd_rn(s, y5);
        s = __fadd_rn(s, y6); s = __fadd_rn(s, y7);
    }
    float mean = __fdiv_rn(s, 256.f);
    float acc = 0.f;
    for (int c = 0; c < CC; c += 8) {
        float y0 = colp[(size_t)(c+0) * LL], y1 = colp[(size_t)(c+1) * LL];
        float y2 = colp[(size_t)(c+2) * LL], y3 = colp[(size_t)(c+3) * LL];
        float y4 = colp[(size_t)(c+4) * LL], y5 = colp[(size_t)(c+5) * LL];
        float y6 = colp[(size_t)(c+6) * LL], y7 = colp[(size_t)(c+7) * LL];
        float d0 = __fsub_rn(y0, mean), d1 = __fsub_rn(y1, mean);
        float d2 = __fsub_rn(y2, mean), d3 = __fsub_rn(y3, mean);
        float d4 = __fsub_rn(y4, mean), d5 = __fsub_rn(y5, mean);
        float d6 = __fsub_rn(y6, mean), d7 = __fsub_rn(y7, mean);
        acc = fmaf(d0, d0, acc); acc = fmaf(d1, d1, acc);
        acc = fmaf(d2, d2, acc); acc = fmaf(d3, d3, acc);
        acc = fmaf(d4, d4, acc); acc = fmaf(d5, d5, acc);
        acc = fmaf(d6, d6, acc); acc = fmaf(d7, d7, acc);
    }
    float var = __fdiv_rn(acc, 256.f);
    float denom = __fadd_rn(sqrtf(var), 1e-6f);
    float* dcol = dst + (size_t)b * CC * LL + l;
    for (int c = 0; c < CC; c += 4) {
        float y0 = colp[(size_t)(c+0) * LL], y1 = colp[(size_t)(c+1) * LL];
        float y2 = colp[(size_t)(c+2) * LL], y3 = colp[(size_t)(c+3) * LL];
        dcol[(size_t)(c+0) * LL] = __fadd_rn(__fdiv_rn(__fmul_rn(gamma[c+0], __fsub_rn(y0, mean)), denom), beta[c+0]);
        dcol[(size_t)(c+1) * LL] = __fadd_rn(__fdiv_rn(__fmul_rn(gamma[c+1], __fsub_rn(y1, mean)), denom), beta[c+1]);
        dcol[(size_t)(c+2) * LL] = __fadd_rn(__fdiv_rn(__fmul_rn(gamma[c+2], __fsub_rn(y2, mean)), denom), beta[c+2]);
        dcol[(size_t)(c+3) * LL] = __fadd_rn(__fdiv_rn(__fmul_rn(gamma[c+3], __fsub_rn(y3, mean)), denom), beta[c+3]);
    }
}

// ---------------- tiled fp32 GEMM (K16, f32x2-packed output pairs) ----------------
__global__ void gemm_kernel(const float* __restrict__ W, int mode) {
    const float* X; float* Y; int M;
    if (mode == 0)      { X = g_xc;  Y = g_kv; M = 512; }
    else if (mode == 1) { X = g_xq;  Y = g_qp; M = 256; }
    else                { X = g_oin; Y = g_o2; M = 256; }

    __shared__ float As[16][68];
    __shared__ float Bs[16][64];

    int n0 = blockIdx.x * 64;
    int m0 = blockIdx.y * 64;
    int b  = n0 >> 12;
    int l0 = n0 & 4095;
    const float* Xb = X + (size_t)b * CC * LL;
    float* Yb = Y + (size_t)b * M * LL;

    int tid = threadIdx.x;
    int tx = tid & 15;
    int ty = tid >> 4;
    ull acc01[4], acc23[4];
#pragma unroll
    for (int i = 0; i < 4; i++) { acc01[i] = pk2(0.f, 0.f); acc23[i] = pk2(0.f, 0.f); }

    for (int k0 = 0; k0 < CC; k0 += 16) {
#pragma unroll
        for (int idx = tid; idx < 64 * 16; idx += 256) {
            int i = idx >> 4, j = idx & 15;
            As[j][i] = W[(size_t)(m0 + i) * CC + k0 + j];
        }
#pragma unroll
        for (int idx = tid; idx < 16 * 64; idx += 256) {
            int i = idx >> 6, j = idx & 63;
            Bs[i][j] = Xb[(size_t)(k0 + i) * LL + l0 + j];
        }
        __syncthreads();
#pragma unroll
        for (int kk = 0; kk < 16; kk++) {
            float a[4];
            *(float4*)a = *(const float4*)&As[kk][ty * 4];
            ull b01 = *(const ull*)&Bs[kk][tx * 4];
            ull b23 = *(const ull*)&Bs[kk][tx * 4 + 2];
#pragma unroll
            for (int i = 0; i < 4; i++) {
                ull ap = pk2(a[i], a[i]);
                acc01[i] = fma2(ap, b01, acc01[i]);
                acc23[i] = fma2(ap, b23, acc23[i]);
            }
        }
        __syncthreads();
    }
#pragma unroll
    for (int i = 0; i < 4; i++) {
        float o0, o1, o2, o3;
        upk2(acc01[i], o0, o1);
        upk2(acc23[i], o2, o3);
        float4 o = make_float4(o0, o1, o2, o3);
        *(float4*)&Yb[(size_t)(m0 + ty * 4 + i) * LL + l0 + tx * 4] = o;
    }
}

// ---------------- fold + optional l2norm + transpose ----------------
__global__ void fold_kernel(int mode) {
    const float* src; float* dst; int rows, off, doNorm;
    if (mode == 0)      { src = g_qp; dst = g_qt; rows = 256; off = 0;   doNorm = 1; }
    else if (mode == 1) { src = g_kv; dst = g_kt; rows = 512; off = 0;   doNorm = 1; }
    else                { src = g_kv; dst = g_vt; rows = 512; off = 256; doNorm = 0; }

    __shared__ float s[32][33];
    __shared__ float nrm[32];
    int bh = blockIdx.y;
    int b = bh >> 3, h = bh & 7;
    int l0 = blockIdx.x * 32;
    int x = threadIdx.x, y = threadIdx.y;

    s[y][x] = src[((size_t)b * rows + off + h * 32 + y) * LL + l0 + x];
    __syncthreads();
    if (y == 0) {
        float ss = 0.f;
#pragma unroll
        for (int d = 0; d < 32; d++) { float v = s[d][x]; ss = fmaf(v, v, ss); }
        nrm[x] = fmaxf(sqrtf(ss), 1e-12f);
    }
    __syncthreads();
    float v = s[x][y];
    if (doNorm) v = __fdiv_rn(v, nrm[y]);
    dst[((size_t)bh * LL + l0 + y) * DD + x] = v;
}

// ---------------- kmeans init ----------------
__global__ void kinit_kernel() {
    __shared__ float cs[DD];
    int j = blockIdx.x, d = threadIdx.x;
    float v = g_qt[j * DD + d];
    g_cent[j * DD + d] = v;
    cs[d] = v;
    __syncthreads();
    if (d == 0) g_cnorm[j] = row_reduce_sq(cs);
}

// ---------------- assignment: f32x2-packed cluster pairs (bit-frozen chains) ----------------
__global__ void __launch_bounds__(256) assign_kernel(int mode) {
    __shared__ float2 sc2[(KCL/2) * DD];
    __shared__ float scn[KCL];
    __shared__ int   cnt[KCL];
    int tid = threadIdx.x;
    for (int i = tid; i < (KCL/2) * DD; i += 256) {
        int jp = i >> 5, k = i & 31;
        sc2[i] = make_float2(g_cent[(2*jp) * DD + k], g_cent[(2*jp+1) * DD + k]);
    }
    if (tid < KCL) { scn[tid] = g_cnorm[tid]; cnt[tid] = 0; }
    __syncthreads();

    const float* pts = (mode == 0) ? g_qt : g_kt;
    int p = blockIdx.x * 256 + tid;

    float x[32];
    const float4* xp = (const float4*)(pts + (size_t)p * DD);
#pragma unroll
    for (int i = 0; i < 8; i++) ((float4*)x)[i] = xp[i];
    float xx = 0.f;
#pragma unroll
    for (int d = 0; d < 32; d++) xx = fmaf(x[d], x[d], xx);
    ull xb[32];
#pragma unroll
    for (int d = 0; d < 32; d++) xb[d] = pk2(x[d], x[d]);

    float best = 3.4e38f; int bj = 0;
    for (int j4 = 0; j4 < KCL; j4 += 4) {
        int jp = j4 >> 1;
        ull dA = pk2(0.f, 0.f), dB = pk2(0.f, 0.f);
        const ull* cA = (const ull*)(sc2 + jp * DD);
        const ull* cB = (const ull*)(sc2 + (jp + 1) * DD);
#pragma unroll
        for (int k = 0; k < 32; k++) {
            dA = fma2(xb[k], cA[k], dA);
            dB = fma2(xb[k], cB[k], dB);
        }
        float d0, d1, d2, d3;
        upk2(dA, d0, d1);
        upk2(dB, d2, d3);
        float s0 = __fadd_rn(__fsub_rn(xx, __fmul_rn(2.f, d0)), scn[j4]);
        float s1 = __fadd_rn(__fsub_rn(xx, __fmul_rn(2.f, d1)), scn[j4 + 1]);
        float s2 = __fadd_rn(__fsub_rn(xx, __fmul_rn(2.f, d2)), scn[j4 + 2]);
        float s3 = __fadd_rn(__fsub_rn(xx, __fmul_rn(2.f, d3)), scn[j4 + 3]);
        if (s0 < best) { best = s0; bj = j4; }
        if (s1 < best) { best = s1; bj = j4 + 1; }
        if (s2 < best) { best = s2; bj = j4 + 2; }
        if (s3 < best) { best = s3; bj = j4 + 3; }
    }
    g_assign[p] = bj;

    if (mode == 0) {
        int lane = tid & 31;
        unsigned m = __match_any_sync(0xffffffffu, bj);
        if (lane == __ffs(m) - 1) atomicAdd(&cnt[bj], __popc(m));
        __syncthreads();
        for (int i = tid; i < KCL; i += 256)
            g_bcnt[i * 256 + blockIdx.x] = cnt[i];       // transposed
    } else {
        const float* xo = pts + (size_t)p * DD;
        const float* co = g_cent + bj * DD;
        float a0 = 0.f, a1 = 0.f, a2 = 0.f, a3 = 0.f;
#pragma unroll
        for (int i = 0; i < 8; i++) {
            a0 = __fadd_rn(a0, fabsf(__fsub_rn(co[4*i+0], xo[4*i+0])));
            a1 = __fadd_rn(a1, fabsf(__fsub_rn(co[4*i+1], xo[4*i+1])));
            a2 = __fadd_rn(a2, fabsf(__fsub_rn(co[4*i+2], xo[4*i+2])));
            a3 = __fadd_rn(a3, fabsf(__fsub_rn(co[4*i+3], xo[4*i+3])));
        }
        g_kdist[p] = __fadd_rn(__fadd_rn(a0, a2), __fadd_rn(a1, a3));
    }
}

// ---------------- per-cluster scan over blocks (parallel; integers, exact) ----------------
__global__ void scan_kernel() {   // 256 blocks (one per cluster), 256 threads
    __shared__ int wsum[8];
    int j = blockIdx.x, b = threadIdx.x;
    int v = g_bcnt[j * 256 + b];
    int excl = block_excl_scan_256(v, wsum);
    g_bstart[j * 256 + b] = excl;
    if (b == 255) g_ctot[j] = excl + v;
}

// ---------------- scatter: parallel, order-preserving; cbase prefix inlined ----------------
__global__ void scatter_kernel() {
    __shared__ int whist[8][KCL];
    __shared__ int cb[KCL];
    __shared__ int wsum[8];
    int tid = threadIdx.x, blk = blockIdx.x;
    int w = tid >> 5, lane = tid & 31;
    for (int i = tid; i < 8 * KCL; i += 256) ((int*)whist)[i] = 0;
    // inline exclusive prefix of g_ctot -> cb
    int tv = g_ctot[tid];
    int excl = block_excl_scan_256(tv, wsum);
    cb[tid] = excl;
    __syncthreads();
    int p = blk * 256 + tid;
    int a = g_assign[p];
    unsigned m = __match_any_sync(0xffffffffu, a);
    int rank = __popc(m & ((1u << lane) - 1u));
    if (lane == __ffs(m) - 1) whist[w][a] = __popc(m);
    __syncthreads();
    int c = tid, s = 0;
#pragma unroll
    for (int ww = 0; ww < 8; ww++) { int t = whist[ww][c]; whist[ww][c] = s; s += t; }
    __syncthreads();
    int pos = cb[a] + g_bstart[a * 256 + blk] + whist[w][a] + rank;
    g_list[pos] = p;
}

// ---------------- centroids: 8 clusters/block; cbase prefix inlined ----------------
__global__ void centroid_kernel() {   // grid 32, block 256
    __shared__ float cs[8][DD];
    __shared__ int cb[KCL];
    __shared__ int wsum[8];
    int tid = threadIdx.x;
    int w = tid >> 5, d = tid & 31;
    int tv = g_ctot[tid];
    int excl = block_excl_scan_256(tv, wsum);
    cb[tid] = excl;
    __syncthreads();
    int j = blockIdx.x * 8 + w;
    int base = cb[j];
    int tot  = g_ctot[j];
    float s = 0.f;
    int i = 0;
    for (; i + 8 <= tot; i += 8) {
        int p0 = g_list[base + i + 0];
        int p1 = g_list[base + i + 1];
        int p2 = g_list[base + i + 2];
        int p3 = g_list[base + i + 3];
        int p4 = g_list[base + i + 4];
        int p5 = g_list[base + i + 5];
        int p6 = g_list[base + i + 6];
        int p7 = g_list[base + i + 7];
        float y0 = g_qt[(size_t)p0 * DD + d];
        float y1 = g_qt[(size_t)p1 * DD + d];
        float y2 = g_qt[(size_t)p2 * DD + d];
        float y3 = g_qt[(size_t)p3 * DD + d];
        float y4 = g_qt[(size_t)p4 * DD + d];
        float y5 = g_qt[(size_t)p5 * DD + d];
        float y6 = g_qt[(size_t)p6 * DD + d];
        float y7 = g_qt[(size_t)p7 * DD + d];
        s = __fadd_rn(s, y0);
        s = __fadd_rn(s, y1);
        s = __fadd_rn(s, y2);
        s = __fadd_rn(s, y3);
        s = __fadd_rn(s, y4);
        s = __fadd_rn(s, y5);
        s = __fadd_rn(s, y6);
        s = __fadd_rn(s, y7);
    }
    for (; i < tot; i++)
        s = __fadd_rn(s, g_qt[(size_t)g_list[base + i] * DD + d]);

    float old = g_cent[j * DD + d];
    float cntf = (float)tot;
    float newc = (tot > 0) ? __fdiv_rn(s, fmaxf(cntf, 1.f)) : old;
    g_cent[j * DD + d] = newc;
    cs[w][d] = newc;
    __syncwarp();
    if (d == 0) g_cnorm[j] = row_reduce_sq(cs[w]);
}

// ---------------- top-256 by k_dist (desc value, asc index) via bitonic sort ----------------
__global__ void topk_kernel() {
    __shared__ unsigned long long s[LL];
    int bh = blockIdx.x, tid = threadIdx.x;   // 1024 threads
    for (int i = tid; i < LL; i += 1024) {
        float v = g_kdist[(size_t)bh * LL + i];
        unsigned u = __float_as_uint(v);
        u = (u & 0x80000000u) ? ~u : (u | 0x80000000u);
        u = ~u;
        s[i] = ((unsigned long long)u << 32) | (unsigned)i;
    }
    __syncthreads();
    for (int k = 2; k <= LL; k <<= 1) {
        for (int j = k >> 1; j > 0; j >>= 1) {
            for (int i = tid; i < LL; i += 1024) {
                int ixj = i ^ j;
                if (ixj > i) {
                    bool up = ((i & k) == 0);
                    unsigned long long a = s[i], b = s[ixj];
                    if ((a > b) == up) { s[i] = b; s[ixj] = a; }
                }
            }
            __syncthreads();
        }
    }
    if (tid < KCL) g_topk[bh * KCL + tid] = (int)(s[tid] & 0xffffffffu);
}

// ---------------- gather selected k/v ----------------
__global__ void gather_kernel() {
    int idx = blockIdx.x * 256 + threadIdx.x;
    int d = idx & 31;
    int r = idx >> 5;
    int bh = r >> 8;
    int src = g_topk[r];
    g_ksel[idx] = g_kt[((size_t)bh * LL + src) * DD + d];
    g_vsel[idx] = g_vt[((size_t)bh * LL + src) * DD + d];
}

// ---------------- attention: no-max softmax (unit vectors -> dot in [-1,1]),
// packed dots across key pairs, __expf. Post-decision; tolerance-protected. ----------------
__global__ void attn_kernel() {
    __shared__ ull  kss[64 * DD];     // interleaved: (key2j, key2j+1) per k slot, 128-key chunk
    __shared__ float vs[128 * DD];
    int bh = blockIdx.y;
    int b = bh >> 3, h = bh & 7;
    int l = blockIdx.x * 128 + threadIdx.x;

    float q[32];
    const float4* qp = (const float4*)(g_qt + ((size_t)bh * LL + l) * DD);
#pragma unroll
    for (int i = 0; i < 8; i++) ((float4*)q)[i] = qp[i];
    ull qb[32];
#pragma unroll
    for (int k = 0; k < 32; k++) qb[k] = pk2(q[k], q[k]);

    float lsum = 0.f;
    ull accp[16];
#pragma unroll
    for (int d2 = 0; d2 < 16; d2++) accp[d2] = pk2(0.f, 0.f);

    for (int c = 0; c < 2; c++) {
        __syncthreads();
        for (int i = threadIdx.x; i < 128 * DD; i += 128) {
            int j = i >> 5, k = i & 31;
            float kvv = g_ksel[(size_t)bh * KCL * DD + c * 128 * DD + i];
            ((float*)kss)[(((j >> 1) * DD + k) << 1) | (j & 1)] = kvv;
            vs[i] = g_vsel[(size_t)bh * KCL * DD + c * 128 * DD + i];
        }
        __syncthreads();
        for (int jp = 0; jp < 64; jp++) {
            ull dp = pk2(0.f, 0.f);
            const ull* kp = kss + jp * DD;
#pragma unroll
            for (int k = 0; k < 32; k++) dp = fma2(qb[k], kp[k], dp);
            float dot0, dot1;
            upk2(dp, dot0, dot1);
            float p0 = __expf(dot0);
            float p1 = __expf(dot1);
            lsum = __fadd_rn(__fadd_rn(lsum, p0), p1);
            ull pp0 = pk2(p0, p0), pp1 = pk2(p1, p1);
            const ull* v0 = (const ull*)(vs + (2 * jp) * DD);
            const ull* v1 = (const ull*)(vs + (2 * jp + 1) * DD);
#pragma unroll
            for (int d2 = 0; d2 < 16; d2++) {
                accp[d2] = fma2(pp0, v0[d2], accp[d2]);
                accp[d2] = fma2(pp1, v1[d2], accp[d2]);
            }
        }
    }
    float inv = 1.f / lsum;
#pragma unroll
    for (int d2 = 0; d2 < 16; d2++) {
        float a0, a1;
        upk2(accp[d2], a0, a1);
        g_oin[((size_t)b * CC + h * 32 + 2*d2)     * LL + l] = a0 * inv;
        g_oin[((size_t)b * CC + h * 32 + 2*d2 + 1) * LL + l] = a1 * inv;
    }
}

// ---------------- final LN + scaled residual (MLP-8 batched loads, chain frozen) ----------------
__global__ void final_kernel(const float* __restrict__ qsrc,
                             const float* __restrict__ gamma,
                             const float* __restrict__ beta,
                             const float* __restrict__ gs,
                             float* __restrict__ out) {
    int n = blockIdx.x * blockDim.x + threadIdx.x;
    int b = n >> 12, l = n & 4095;
    const float* colp = g_o2 + (size_t)b * CC * LL + l;
    float s = 0.f;
    for (int c = 0; c < CC; c += 8) {
        float y0 = colp[(size_t)(c+0) * LL], y1 = colp[(size_t)(c+1) * LL];
        float y2 = colp[(size_t)(c+2) * LL], y3 = colp[(size_t)(c+3) * LL];
        float y4 = colp[(size_t)(c+4) * LL], y5 = colp[(size_t)(c+5) * LL];
        float y6 = colp[(size_t)(c+6) * LL], y7 = colp[(size_t)(c+7) * LL];
        s = __fadd_rn(s, y0); s = __fadd_rn(s, y1);
        s = __fadd_rn(s, y2); s = __fadd_rn(s, y3);
        s = __fadd_rn(s, y4); s = __fadd_rn(s, y5);
        s = __fadd_rn(s, y6); s = __fadd_rn(s, y7);
    }
    float mean = __fdiv_rn(s, 256.f);
    float acc = 0.f;
    for (int c = 0; c < CC; c += 8) {
        float y0 = colp[(size_t)(c+0) * LL], y1 = colp[(size_t)(c+1) * LL];
        float y2 = colp[(size_t)(c+2) * LL], y3 = colp[(size_t)(c+3) * LL];
        float y4 = colp[(size_t)(c+4) * LL], y5 = colp[(size_t)(c+5) * LL];
        float y6 = colp[(size_t)(c+6) * LL], y7 = colp[(size_t)(c+7) * LL];
        float d0 = __fsub_rn(y0, mean), d1 = __fsub_rn(y1, mean);
        float d2 = __fsub_rn(y2, mean), d3 = __fsub_rn(y3, mean);
        float d4 = __fsub_rn(y4, mean), d5 = __fsub_rn(y5, mean);
        float d6 = __fsub_rn(y6, mean), d7 = __fsub_rn(y7, mean);
        acc = fmaf(d0, d0, acc); acc = fmaf(d1, d1, acc);
        acc = fmaf(d2, d2, acc); acc = fmaf(d3, d3, acc);
        acc = fmaf(d4, d4, acc); acc = fmaf(d5, d5, acc);
        acc = fmaf(d6, d6, acc); acc = fmaf(d7, d7, acc);
    }
    float var = __fdiv_rn(acc, 256.f);
    float denom = __fadd_rn(sqrtf(var), 1e-6f);
    float g = gs[0];
    const float* qcol = qsrc + (size_t)b * CC * LL + l;
    float* ocol = out + (size_t)b * CC * LL + l;
    for (int c = 0; c < CC; c += 4) {
        float y0 = colp[(size_t)(c+0) * LL], y1 = colp[(size_t)(c+1) * LL];
        float y2 = colp[(size_t)(c+2) * LL], y3 = colp[(size_t)(c+3) * LL];
        float r0 = qcol[(size_t)(c+0) * LL], r1 = qcol[(size_t)(c+1) * LL];
        float r2 = qcol[(size_t)(c+2) * LL], r3 = qcol[(size_t)(c+3) * LL];
        float o0 = __fadd_rn(__fdiv_rn(__fmul_rn(gamma[c+0], __fsub_rn(y0, mean)), denom), beta[c+0]);
        float o1 = __fadd_rn(__fdiv_rn(__fmul_rn(gamma[c+1], __fsub_rn(y1, mean)), denom), beta[c+1]);
        float o2 = __fadd_rn(__fdiv_rn(__fmul_rn(gamma[c+2], __fsub_rn(y2, mean)), denom), beta[c+2]);
        float o3 = __fadd_rn(__fdiv_rn(__fmul_rn(gamma[c+3], __fsub_rn(y3, mean)), denom), beta[c+3]);
        ocol[(size_t)(c+0) * LL] = fmaf(g, o0, r0);
        ocol[(size_t)(c+1) * LL] = fmaf(g, o1, r1);
        ocol[(size_t)(c+2) * LL] = fmaf(g, o2, r2);
        ocol[(size_t)(c+3) * LL] = fmaf(g, o3, r3);
    }
}

// ---------------- launch ----------------
extern "C" void kernel_launch(void* const* d_in, const int* in_sizes, int n_in,
                              void* d_out, int out_size) {
    const float* qsrc   = (const float*)d_in[0];
    const float* ctx    = (const float*)d_in[1];
    const float* w_q    = (const float*)d_in[2];
    const float* w_kv   = (const float*)d_in[3];
    const float* w_out  = (const float*)d_in[4];
    const float* lnc_g  = (const float*)d_in[5];
    const float* lnc_b  = (const float*)d_in[6];
    const float* lnq_g  = (const float*)d_in[7];
    const float* lnq_b  = (const float*)d_in[8];
    const float* lno_g  = (const float*)d_in[9];
    const float* lno_b  = (const float*)d_in[10];
    const float* gs     = (const float*)d_in[11];
    float* out = (float*)d_out;

    // LN both inputs
    ln_kernel<<<32, 256>>>(ctx,  lnc_g, lnc_b, 0);
    ln_kernel<<<32, 256>>>(qsrc, lnq_g, lnq_b, 1);

    // projections
    gemm_kernel<<<dim3(128, 8), 256>>>(w_kv, 0);   // kv: 512 rows
    gemm_kernel<<<dim3(128, 4), 256>>>(w_q,  1);   // q: 256 rows

    // fold + l2norm + transpose
    fold_kernel<<<dim3(128, NBH), dim3(32, 32)>>>(0);  // q
    fold_kernel<<<dim3(128, NBH), dim3(32, 32)>>>(1);  // k
    fold_kernel<<<dim3(128, NBH), dim3(32, 32)>>>(2);  // v

    // kmeans (deterministic, reference-order arithmetic)
    kinit_kernel<<<KCL, 32>>>();
    for (int it = 0; it < NITER; it++) {
        assign_kernel<<<256, 256>>>(0);
        scan_kernel<<<256, 256>>>();
        scatter_kernel<<<256, 256>>>();
        centroid_kernel<<<32, 256>>>();
    }

    // k assignment + L1 distance to its centroid
    assign_kernel<<<256, 256>>>(1);

    // top-256 per bh, gather
    topk_kernel<<<NBH, 1024>>>();
    gather_kernel<<<NBH * KCL * DD / 256, 256>>>();

    // attention + unfold
    attn_kernel<<<dim3(32, NBH), 128>>>();

    // output projection
    gemm_kernel<<<dim3(128, 4), 256>>>(w_out, 2);

    // final LN + residual
    final_kernel<<<32, 256>>>(qsrc, lno_g, lno_b, gs, out);
}